// round 10
// baseline (speedup 1.0000x reference)
#include <cuda_runtime.h>
#include <cuda_bf16.h>
#include <cstdint>

typedef uint32_t u32;

#define BATCHN 131072
#define MROWS  128            // 4 warps x 32 rows
#define NBLOCKS (BATCHN / MROWS)
#define TPB 128

// smem byte layout
#define OFF_W    0            // 8 weight tiles, B-frag packed, 16KB each
#define W_TILE   16384
#define OFF_A    131072       // 4 warps x 3 activation buffers x 8KB (hi 4K + lo 4K)
#define ABUF     8192
#define OFF_BIAS 229376       // 6 x 64 fp32
#define OFF_TV   230912       // 64 fp32
#define SMEM_BYTES 231168

extern __shared__ char smc[];

// m16n8k16 row.col f32.bf16.bf16.f32
static __device__ __forceinline__ void mma_bf16(float* c, const u32* a, u32 b0, u32 b1) {
    asm volatile("mma.sync.aligned.m16n8k16.row.col.f32.bf16.bf16.f32 "
        "{%0,%1,%2,%3},{%4,%5,%6,%7},{%8,%9},{%0,%1,%2,%3};"
        : "+f"(c[0]), "+f"(c[1]), "+f"(c[2]), "+f"(c[3])
        : "r"(a[0]), "r"(a[1]), "r"(a[2]), "r"(a[3]), "r"(b0), "r"(b1));
}

static __device__ __forceinline__ u32 pack2(__nv_bfloat16 a, __nv_bfloat16 b) {
    __nv_bfloat162 t(a, b);
    return *reinterpret_cast<u32*>(&t);
}
static __device__ __forceinline__ void split(float v, __nv_bfloat16& h, __nv_bfloat16& l) {
    h = __float2bfloat16(v);
    l = __float2bfloat16(v - __bfloat162float(h));
}
static __device__ __forceinline__ void splitpk(float2 v, u32& hp, u32& lp) {
    __nv_bfloat16 h0, l0, h1, l1;
    split(v.x, h0, l0); split(v.y, h1, l1);
    hp = pack2(h0, h1); lp = pack2(l0, l1);
}
static __device__ __forceinline__ float lrelu(float v) {
    return v > 0.f ? v : 0.01f * v;
}
static __device__ __forceinline__ void zeroC(float* C, int n) {
#pragma unroll
    for (int i = 0; i < n; i++) C[i] = 0.f;
}

// activation buffer addressing: tile t in {0,1}
#define AB(buf, kt, t, lane) ((buf) + ((((kt) * 2 + (t)) * 32 + (lane)) << 4))

// ---- C{0,1} += X(smem) @ Wtile : 64x64 unit, 2 M-tiles, 3-pass bf16 emulation ----
static __device__ __forceinline__ void gemm_unit(float C0[32], float C1[32],
                                                 const char* abuf, const char* wt,
                                                 int lane) {
#pragma unroll 1
    for (int kt = 0; kt < 4; kt++) {
        const uint4 Ah0 = *(const uint4*)AB(abuf, kt, 0, lane);
        const uint4 Al0 = *(const uint4*)(AB(abuf, kt, 0, lane) + 4096);
        const uint4 Ah1 = *(const uint4*)AB(abuf, kt, 1, lane);
        const uint4 Al1 = *(const uint4*)(AB(abuf, kt, 1, lane) + 4096);
#pragma unroll
        for (int nt = 0; nt < 8; nt++) {
            const uint4 B = *(const uint4*)(wt + (((kt * 8 + nt) * 32 + lane) << 4));
            mma_bf16(C0 + nt * 4, (const u32*)&Ah0, B.x, B.y);
            mma_bf16(C1 + nt * 4, (const u32*)&Ah1, B.x, B.y);
            mma_bf16(C0 + nt * 4, (const u32*)&Ah0, B.z, B.w);
            mma_bf16(C1 + nt * 4, (const u32*)&Ah1, B.z, B.w);
            mma_bf16(C0 + nt * 4, (const u32*)&Al0, B.x, B.y);
            mma_bf16(C1 + nt * 4, (const u32*)&Al1, B.x, B.y);
        }
    }
}

// ---- one tile's C (+bias, opt lrelu) -> frag-packed smem (lane-private) ----
static __device__ __forceinline__ void epi_store(const float C[32], const float* bias,
                                                 bool relu, char* dst, int t, int lane) {
    const int cb = (lane & 3) * 2;
    u32 h[16], l[16];
#pragma unroll
    for (int nt = 0; nt < 8; nt++) {
        const float bb0 = bias[8 * nt + cb], bb1 = bias[8 * nt + cb + 1];
        float v0 = C[nt * 4 + 0] + bb0, v1 = C[nt * 4 + 1] + bb1;
        float v2 = C[nt * 4 + 2] + bb0, v3 = C[nt * 4 + 3] + bb1;
        if (relu) { v0 = lrelu(v0); v1 = lrelu(v1); v2 = lrelu(v2); v3 = lrelu(v3); }
        const int o = (nt >> 1) * 4 + (nt & 1) * 2;
        splitpk(make_float2(v0, v1), h[o], l[o]);
        splitpk(make_float2(v2, v3), h[o + 1], l[o + 1]);
    }
#pragma unroll
    for (int kt = 0; kt < 4; kt++) {
        *(uint4*)AB(dst, kt, t, lane) =
            make_uint4(h[4 * kt], h[4 * kt + 1], h[4 * kt + 2], h[4 * kt + 3]);
        *(uint4*)(AB(dst, kt, t, lane) + 4096) =
            make_uint4(l[4 * kt], l[4 * kt + 1], l[4 * kt + 2], l[4 * kt + 3]);
    }
}

// ---- gather 2 embedding rows into one tile of a frag-packed buffer ----
static __device__ __forceinline__ void gather_tile(char* dst, int t, const float* e0,
                                                   const float* e1, int q, int lane) {
#pragma unroll
    for (int kt = 0; kt < 4; kt++) {
        float2 a = ((const float2*)e0)[8 * kt + q];
        float2 b = ((const float2*)e1)[8 * kt + q];
        float2 c = ((const float2*)e0)[8 * kt + q + 4];
        float2 d = ((const float2*)e1)[8 * kt + q + 4];
        u32 h0, l0, h1, l1, h2, l2, h3, l3;
        splitpk(a, h0, l0); splitpk(b, h1, l1);
        splitpk(c, h2, l2); splitpk(d, h3, l3);
        *(uint4*)AB(dst, kt, t, lane)          = make_uint4(h0, h1, h2, h3);
        *(uint4*)(AB(dst, kt, t, lane) + 4096) = make_uint4(l0, l1, l2, l3);
    }
}

#define WT(i) (smc + OFF_W + (i) * W_TILE)

// NOT mlp, fully in-place in buf
static __device__ __noinline__ void mlp_not(char* buf, const float* bs, int lane) {
    float C0[32], C1[32];
    zeroC(C0, 32); zeroC(C1, 32);
    gemm_unit(C0, C1, buf, WT(0), lane);
    epi_store(C0, bs, true, buf, 0, lane);
    epi_store(C1, bs, true, buf, 1, lane);
    zeroC(C0, 32); zeroC(C1, 32);
    gemm_unit(C0, C1, buf, WT(1), lane);
    epi_store(C0, bs + 64, false, buf, 0, lane);
    epi_store(C1, bs + 64, false, buf, 1, lane);
}

// AND/OR mlp: result and hidden in x1's buffer; tiles (ta,ta+1,ta+2)=(W1a,W1b,W2)
static __device__ __noinline__ void mlp2(char* x1, char* x2, const char* ta,
                                         const float* bs, int lane) {
    float C0[32], C1[32];
    zeroC(C0, 32); zeroC(C1, 32);
    gemm_unit(C0, C1, x1, ta, lane);
    gemm_unit(C0, C1, x2, ta + W_TILE, lane);
    epi_store(C0, bs, true, x1, 0, lane);
    epi_store(C1, bs, true, x1, 1, lane);
    zeroC(C0, 32); zeroC(C1, 32);
    gemm_unit(C0, C1, x1, ta + 2 * W_TILE, lane);
    epi_store(C0, bs + 64, false, x1, 0, lane);
    epi_store(C1, bs + 64, false, x1, 1, lane);
}

// final OR + cosine; hidden in scratch buffer hid (x1 preserved)
static __device__ __noinline__ void mlp2_cos(char* x1, char* x2, char* hid,
                                             const char* ta, const float* bs,
                                             const float* tvs, float tvd,
                                             float* outp, int g0, int lane) {
    float C0[32], C1[32];
    zeroC(C0, 32); zeroC(C1, 32);
    gemm_unit(C0, C1, x1, ta, lane);
    gemm_unit(C0, C1, x2, ta + W_TILE, lane);
    epi_store(C0, bs, true, hid, 0, lane);
    epi_store(C1, bs, true, hid, 1, lane);
    zeroC(C0, 32); zeroC(C1, 32);
    gemm_unit(C0, C1, hid, ta + 2 * W_TILE, lane);

    const float* b2 = bs + 64;
    const int cb = (lane & 3) * 2;
    float nu[4] = {0.f, 0.f, 0.f, 0.f}, nr[4] = {0.f, 0.f, 0.f, 0.f};
#pragma unroll
    for (int nt = 0; nt < 8; nt++) {
        const int c0 = 8 * nt + cb;
        const float bb0 = b2[c0], bb1 = b2[c0 + 1];
        const float t0 = tvs[c0], t1 = tvs[c0 + 1];
        const float* Cs[2] = { C0 + nt * 4, C1 + nt * 4 };
#pragma unroll
        for (int t = 0; t < 2; t++) {
            float v0 = Cs[t][0] + bb0, v1 = Cs[t][1] + bb1;
            float v2 = Cs[t][2] + bb0, v3 = Cs[t][3] + bb1;
            nu[2 * t + 0] = fmaf(v0, t0, fmaf(v1, t1, nu[2 * t + 0]));
            nr[2 * t + 0] = fmaf(v0, v0, fmaf(v1, v1, nr[2 * t + 0]));
            nu[2 * t + 1] = fmaf(v2, t0, fmaf(v3, t1, nu[2 * t + 1]));
            nr[2 * t + 1] = fmaf(v2, v2, fmaf(v3, v3, nr[2 * t + 1]));
        }
    }
#pragma unroll
    for (int off = 1; off <= 2; off <<= 1)
#pragma unroll
        for (int j = 0; j < 4; j++) {
            nu[j] += __shfl_xor_sync(~0u, nu[j], off);
            nr[j] += __shfl_xor_sync(~0u, nr[j], off);
        }
    if ((lane & 3) == 0) {
        // j: 0 -> row g0, 1 -> g0+8 (tile0); 2 -> g0+16, 3 -> g0+24 (tile1)
        outp[g0]      = nu[0] / (fmaxf(sqrtf(nr[0]), 1e-8f) * tvd) * 10.0f;
        outp[g0 + 8]  = nu[1] / (fmaxf(sqrtf(nr[1]), 1e-8f) * tvd) * 10.0f;
        outp[g0 + 16] = nu[2] / (fmaxf(sqrtf(nr[2]), 1e-8f) * tvd) * 10.0f;
        outp[g0 + 24] = nu[3] / (fmaxf(sqrtf(nr[3]), 1e-8f) * tvd) * 10.0f;
    }
}

__global__ void __launch_bounds__(TPB, 1)
logicnet_kernel(const int* __restrict__ seq,
                const int* __restrict__ pos_t,
                const int* __restrict__ neg_t,
                const float* __restrict__ item_embed,
                const float* __restrict__ g_tv,
                const float* __restrict__ nW1, const float* __restrict__ nb1,
                const float* __restrict__ nW2, const float* __restrict__ nb2,
                const float* __restrict__ aW1, const float* __restrict__ ab1,
                const float* __restrict__ aW2, const float* __restrict__ ab2,
                const float* __restrict__ oW1, const float* __restrict__ ob1,
                const float* __restrict__ oW2, const float* __restrict__ ob2,
                float* __restrict__ out) {
    const int tid = threadIdx.x, w = tid >> 5, lane = tid & 31;

    // ---- stage weights into B-fragment-packed smem (hi,hi,lo,lo per uint4) ----
    {
        const float* wsrc[8] = { nW1, nW2, aW1, aW1 + 4096, aW2, oW1, oW1 + 4096, oW2 };
#pragma unroll 1
        for (int e = tid; e < 8192; e += TPB) {
            const int t = e >> 10, rem = e & 1023, ktnt = rem >> 5, ln = rem & 31;
            const int k0 = (ktnt >> 3) * 16 + (ln & 3) * 2;
            const int n  = (ktnt & 7) * 8 + (ln >> 2);
            const float* s = wsrc[t];
            const float w00 = s[(k0)     * 64 + n], w01 = s[(k0 + 1) * 64 + n];
            const float w10 = s[(k0 + 8) * 64 + n], w11 = s[(k0 + 9) * 64 + n];
            u32 bh0, bl0, bh1, bl1;
            splitpk(make_float2(w00, w01), bh0, bl0);
            splitpk(make_float2(w10, w11), bh1, bl1);
            *(uint4*)(smc + OFF_W + (size_t)t * W_TILE + ((size_t)ktnt * 32 + ln) * 16) =
                make_uint4(bh0, bh1, bl0, bl1);
        }
        float* sb = (float*)(smc + OFF_BIAS);
        if (tid < 64) {
            sb[tid]       = nb1[tid]; sb[64 + tid]  = nb2[tid];
            sb[128 + tid] = ab1[tid]; sb[192 + tid] = ab2[tid];
            sb[256 + tid] = ob1[tid]; sb[320 + tid] = ob2[tid];
            ((float*)(smc + OFF_TV))[tid] = g_tv[tid];
        }
    }
    __syncthreads();

    const float* BS  = (const float*)(smc + OFF_BIAS);
    const float* tvs = (const float*)(smc + OFF_TV);
    float t2 = 0.f;
#pragma unroll
    for (int c = 0; c < 64; c++) t2 = fmaf(tvs[c], tvs[c], t2);
    const float tvd = fmaxf(sqrtf(t2), 1e-8f);

    // warp owns 32 rows: tile0 -> g0, g0+8; tile1 -> g0+16, g0+24
    const int g0 = blockIdx.x * MROWS + w * 32 + (lane >> 2);
    const int q  = lane & 3;
    char* B0 = smc + OFF_A + (w * 3 + 0) * ABUF;
    char* B1 = smc + OFF_A + (w * 3 + 1) * ABUF;
    char* B2 = smc + OFF_A + (w * 3 + 2) * ABUF;

#define EMB(id) (item_embed + (size_t)(id) * 64)
#define GSEQ(dst, p) do { \
    gather_tile(dst, 0, EMB(seq[g0 * 5 + (p)]),        EMB(seq[(g0 + 8) * 5 + (p)]),  q, lane); \
    gather_tile(dst, 1, EMB(seq[(g0 + 16) * 5 + (p)]), EMB(seq[(g0 + 24) * 5 + (p)]), q, lane); \
} while (0)
#define GTGT(dst, arr) do { \
    gather_tile(dst, 0, EMB((arr)[g0]),      EMB((arr)[g0 + 8]),  q, lane); \
    gather_tile(dst, 1, EMB((arr)[g0 + 16]), EMB((arr)[g0 + 24]), q, lane); \
} while (0)

    GSEQ(B0, 1);                                  // e(seq1)
    mlp_not(B0, BS + 0, lane);                    // n1 -> B0
    GSEQ(B1, 0);                                  // e(seq0)
    mlp2(B1, B0, WT(2), BS + 128, lane);          // int5 = AND(e0,n1) -> B1
    GSEQ(B0, 2);                                  // e(seq2)
    GSEQ(B2, 3);                                  // e(seq3)
    mlp2(B0, B2, WT(5), BS + 256, lane);          // int6 = OR(e2,e3) -> B0
    mlp2(B1, B0, WT(2), BS + 128, lane);          // int7 = AND(int5,int6) -> B1
    mlp_not(B1, BS + 0, lane);                    // NOT(int7) -> B1
    GSEQ(B0, 4);                                  // e(seq4)
    mlp2(B1, B0, WT(5), BS + 256, lane);          // out = OR(n7,e4) -> B1
    mlp_not(B1, BS + 0, lane);                    // enc_not -> B1
    GTGT(B0, pos_t);                              // pos_e
    mlp2_cos(B1, B0, B2, WT(5), BS + 256, tvs, tvd, out, g0, lane);
    GTGT(B0, neg_t);                              // neg_e
    mlp2_cos(B1, B0, B2, WT(5), BS + 256, tvs, tvd, out + BATCHN, g0, lane);
}

extern "C" void kernel_launch(void* const* d_in, const int* in_sizes, int n_in,
                              void* d_out, int out_size) {
    (void)in_sizes; (void)n_in; (void)out_size;
    cudaFuncSetAttribute(logicnet_kernel,
                         cudaFuncAttributeMaxDynamicSharedMemorySize, SMEM_BYTES);
    logicnet_kernel<<<NBLOCKS, TPB, SMEM_BYTES>>>(
        (const int*)d_in[0], (const int*)d_in[1], (const int*)d_in[2],
        (const float*)d_in[3], (const float*)d_in[4],
        (const float*)d_in[5], (const float*)d_in[6],
        (const float*)d_in[7], (const float*)d_in[8],
        (const float*)d_in[9], (const float*)d_in[10],
        (const float*)d_in[11], (const float*)d_in[12],
        (const float*)d_in[13], (const float*)d_in[14],
        (const float*)d_in[15], (const float*)d_in[16],
        (float*)d_out);
}

// round 11
// speedup vs baseline: 1.3134x; 1.3134x over previous
#include <cuda_runtime.h>
#include <cuda_bf16.h>
#include <cstdint>

typedef uint32_t u32;

#define BATCHN 131072
#define WARPS  10
#define TPB    (WARPS * 32)
#define MROWS  (WARPS * 16)                      // 160 rows per CTA
#define NBLOCKS ((BATCHN + MROWS - 1) / MROWS)   // 820

// smem byte layout
#define OFF_W    0                // 8 weight tiles, B-frag packed, 16KB each
#define W_TILE   16384
#define OFF_A    131072           // 10 warps x 2 buffers x 4KB (hi 2K + lo 2K)
#define OFF_BIAS 212992           // 6 x 64 fp32
#define OFF_TV   214528           // 64 fp32
#define SMEM_BYTES 214784

extern __shared__ char smc[];

static __device__ __forceinline__ void mma_bf16(float* c, const u32* a, u32 b0, u32 b1) {
    asm volatile("mma.sync.aligned.m16n8k16.row.col.f32.bf16.bf16.f32 "
        "{%0,%1,%2,%3},{%4,%5,%6,%7},{%8,%9},{%0,%1,%2,%3};"
        : "+f"(c[0]), "+f"(c[1]), "+f"(c[2]), "+f"(c[3])
        : "r"(a[0]), "r"(a[1]), "r"(a[2]), "r"(a[3]), "r"(b0), "r"(b1));
}

static __device__ __forceinline__ u32 pack2(__nv_bfloat16 a, __nv_bfloat16 b) {
    __nv_bfloat162 t(a, b);
    return *reinterpret_cast<u32*>(&t);
}
static __device__ __forceinline__ void split(float v, __nv_bfloat16& h, __nv_bfloat16& l) {
    h = __float2bfloat16(v);
    l = __float2bfloat16(v - __bfloat162float(h));
}
static __device__ __forceinline__ void splitpk(float2 v, u32& hp, u32& lp) {
    __nv_bfloat16 h0, l0, h1, l1;
    split(v.x, h0, l0); split(v.y, h1, l1);
    hp = pack2(h0, h1); lp = pack2(l0, l1);
}
static __device__ __forceinline__ float lrelu(float v) {
    return v > 0.f ? v : 0.01f * v;
}
static __device__ __forceinline__ void zeroC(float* C) {
#pragma unroll
    for (int i = 0; i < 32; i++) C[i] = 0.f;
}

// ---- GEMM unit (64x64, 3-pass bf16 emulation), A from smem buffer ----
static __device__ __forceinline__ void gemm_s(float C[32], const char* ab,
                                              const char* wt, int lane) {
#pragma unroll 2
    for (int kt = 0; kt < 4; kt++) {
        const uint4 Ah = *(const uint4*)(ab + ((kt * 32 + lane) << 4));
        const uint4 Al = *(const uint4*)(ab + 2048 + ((kt * 32 + lane) << 4));
#pragma unroll
        for (int nt = 0; nt < 8; nt++) {
            const uint4 B = *(const uint4*)(wt + (((kt * 8 + nt) * 32 + lane) << 4));
            mma_bf16(C + nt * 4, (const u32*)&Ah, B.x, B.y);
            mma_bf16(C + nt * 4, (const u32*)&Ah, B.z, B.w);
            mma_bf16(C + nt * 4, (const u32*)&Al, B.x, B.y);
        }
    }
}
// ---- GEMM unit, A from registers ----
static __device__ __forceinline__ void gemm_r(float C[32], const u32* Hh, const u32* Hl,
                                              const char* wt, int lane) {
#pragma unroll 2
    for (int kt = 0; kt < 4; kt++) {
#pragma unroll
        for (int nt = 0; nt < 8; nt++) {
            const uint4 B = *(const uint4*)(wt + (((kt * 8 + nt) * 32 + lane) << 4));
            mma_bf16(C + nt * 4, Hh + 4 * kt, B.x, B.y);
            mma_bf16(C + nt * 4, Hh + 4 * kt, B.z, B.w);
            mma_bf16(C + nt * 4, Hl + 4 * kt, B.x, B.y);
        }
    }
}

// ---- C (+bias, opt lrelu) -> A-fragment registers ----
static __device__ __forceinline__ void epi_r(const float C[32], const float* bias,
                                             bool relu, u32* Hh, u32* Hl, int lane) {
    const int cb = (lane & 3) * 2;
#pragma unroll
    for (int nt = 0; nt < 8; nt++) {
        const float bb0 = bias[8 * nt + cb], bb1 = bias[8 * nt + cb + 1];
        float v0 = C[nt * 4 + 0] + bb0, v1 = C[nt * 4 + 1] + bb1;
        float v2 = C[nt * 4 + 2] + bb0, v3 = C[nt * 4 + 3] + bb1;
        if (relu) { v0 = lrelu(v0); v1 = lrelu(v1); v2 = lrelu(v2); v3 = lrelu(v3); }
        const int o = (nt >> 1) * 4 + (nt & 1) * 2;
        splitpk(make_float2(v0, v1), Hh[o], Hl[o]);
        splitpk(make_float2(v2, v3), Hh[o + 1], Hl[o + 1]);
    }
}
// ---- A-frag regs -> smem buffer (lane-private) ----
static __device__ __forceinline__ void st_buf(char* dst, const u32* Hh, const u32* Hl,
                                              int lane) {
#pragma unroll
    for (int kt = 0; kt < 4; kt++) {
        *(uint4*)(dst + ((kt * 32 + lane) << 4)) =
            make_uint4(Hh[4 * kt], Hh[4 * kt + 1], Hh[4 * kt + 2], Hh[4 * kt + 3]);
        *(uint4*)(dst + 2048 + ((kt * 32 + lane) << 4)) =
            make_uint4(Hl[4 * kt], Hl[4 * kt + 1], Hl[4 * kt + 2], Hl[4 * kt + 3]);
    }
}
// ---- gather 2 embedding rows -> A-frag registers ----
static __device__ __forceinline__ void gather_r(u32* Hh, u32* Hl, const float* e0,
                                                const float* e1, int q) {
#pragma unroll
    for (int kt = 0; kt < 4; kt++) {
        float2 a = ((const float2*)e0)[8 * kt + q];
        float2 b = ((const float2*)e1)[8 * kt + q];
        float2 c = ((const float2*)e0)[8 * kt + q + 4];
        float2 d = ((const float2*)e1)[8 * kt + q + 4];
        splitpk(a, Hh[4 * kt + 0], Hl[4 * kt + 0]);
        splitpk(b, Hh[4 * kt + 1], Hl[4 * kt + 1]);
        splitpk(c, Hh[4 * kt + 2], Hl[4 * kt + 2]);
        splitpk(d, Hh[4 * kt + 3], Hl[4 * kt + 3]);
    }
}

#define WT(i) (smc + OFF_W + (i) * W_TILE)

// NOT from smem buf, in place (all reads precede lane-private writes)
static __device__ __forceinline__ void not_s(char* buf, const float* bs, int lane) {
    float C[32]; u32 Hh[16], Hl[16];
    zeroC(C); gemm_s(C, buf, WT(0), lane);
    epi_r(C, bs, true, Hh, Hl, lane);
    zeroC(C); gemm_r(C, Hh, Hl, WT(1), lane);
    epi_r(C, bs + 64, false, Hh, Hl, lane);
    st_buf(buf, Hh, Hl, lane);
}
// NOT from reg X -> buf
static __device__ __forceinline__ void not_r(const u32* Xh, const u32* Xl, char* buf,
                                             const float* bs, int lane) {
    float C[32]; u32 Hh[16], Hl[16];
    zeroC(C); gemm_r(C, Xh, Xl, WT(0), lane);
    epi_r(C, bs, true, Hh, Hl, lane);
    zeroC(C); gemm_r(C, Hh, Hl, WT(1), lane);
    epi_r(C, bs + 64, false, Hh, Hl, lane);
    st_buf(buf, Hh, Hl, lane);
}
// x1 = regs (@W1a), x2 = smem buf (@W1b); result -> buf
static __device__ __forceinline__ void mlp2_rs(const u32* Xh, const u32* Xl, char* buf,
                                               const char* ta, const float* bs, int lane) {
    float C[32]; u32 Hh[16], Hl[16];
    zeroC(C);
    gemm_r(C, Xh, Xl, ta, lane);
    gemm_s(C, buf, ta + W_TILE, lane);
    epi_r(C, bs, true, Hh, Hl, lane);
    zeroC(C); gemm_r(C, Hh, Hl, ta + 2 * W_TILE, lane);
    epi_r(C, bs + 64, false, Hh, Hl, lane);
    st_buf(buf, Hh, Hl, lane);
}
// x1 = smem buf (@W1a), x2 = regs (@W1b); result -> buf
static __device__ __forceinline__ void mlp2_sr(char* buf, const u32* Xh, const u32* Xl,
                                               const char* ta, const float* bs, int lane) {
    float C[32]; u32 Hh[16], Hl[16];
    zeroC(C);
    gemm_s(C, buf, ta, lane);
    gemm_r(C, Xh, Xl, ta + W_TILE, lane);
    epi_r(C, bs, true, Hh, Hl, lane);
    zeroC(C); gemm_r(C, Hh, Hl, ta + 2 * W_TILE, lane);
    epi_r(C, bs + 64, false, Hh, Hl, lane);
    st_buf(buf, Hh, Hl, lane);
}
// both smem; result -> x1
static __device__ __forceinline__ void mlp2_ss(char* x1, char* x2, const char* ta,
                                               const float* bs, int lane) {
    float C[32]; u32 Hh[16], Hl[16];
    zeroC(C);
    gemm_s(C, x1, ta, lane);
    gemm_s(C, x2, ta + W_TILE, lane);
    epi_r(C, bs, true, Hh, Hl, lane);
    zeroC(C); gemm_r(C, Hh, Hl, ta + 2 * W_TILE, lane);
    epi_r(C, bs + 64, false, Hh, Hl, lane);
    st_buf(x1, Hh, Hl, lane);
}
// x1 smem (PRESERVED) @W1a, x2 regs @W1b; cosine epilogue -> out
static __device__ __forceinline__ void mlp2_cos(char* x1, const u32* Xh, const u32* Xl,
                                                const char* ta, const float* bs,
                                                const float* tvs, float tvd,
                                                float* outp, int g0, int lane) {
    float C[32]; u32 Hh[16], Hl[16];
    zeroC(C);
    gemm_s(C, x1, ta, lane);
    gemm_r(C, Xh, Xl, ta + W_TILE, lane);
    epi_r(C, bs, true, Hh, Hl, lane);
    zeroC(C); gemm_r(C, Hh, Hl, ta + 2 * W_TILE, lane);

    const float* b2 = bs + 64;
    const int cb = (lane & 3) * 2;
    float nu0 = 0.f, nr0 = 0.f, nu1 = 0.f, nr1 = 0.f;
#pragma unroll
    for (int nt = 0; nt < 8; nt++) {
        const int c0 = 8 * nt + cb;
        const float bb0 = b2[c0], bb1 = b2[c0 + 1];
        const float t0 = tvs[c0], t1 = tvs[c0 + 1];
        float v0 = C[nt * 4 + 0] + bb0, v1 = C[nt * 4 + 1] + bb1;
        float v2 = C[nt * 4 + 2] + bb0, v3 = C[nt * 4 + 3] + bb1;
        nu0 = fmaf(v0, t0, fmaf(v1, t1, nu0));
        nr0 = fmaf(v0, v0, fmaf(v1, v1, nr0));
        nu1 = fmaf(v2, t0, fmaf(v3, t1, nu1));
        nr1 = fmaf(v2, v2, fmaf(v3, v3, nr1));
    }
#pragma unroll
    for (int off = 1; off <= 2; off <<= 1) {
        nu0 += __shfl_xor_sync(~0u, nu0, off);
        nr0 += __shfl_xor_sync(~0u, nr0, off);
        nu1 += __shfl_xor_sync(~0u, nu1, off);
        nr1 += __shfl_xor_sync(~0u, nr1, off);
    }
    if ((lane & 3) == 0) {
        if (g0 < BATCHN)
            outp[g0]     = nu0 / (fmaxf(sqrtf(nr0), 1e-8f) * tvd) * 10.0f;
        if (g0 + 8 < BATCHN)
            outp[g0 + 8] = nu1 / (fmaxf(sqrtf(nr1), 1e-8f) * tvd) * 10.0f;
    }
}

__global__ void __launch_bounds__(TPB, 1)
logicnet_kernel(const int* __restrict__ seq,
                const int* __restrict__ pos_t,
                const int* __restrict__ neg_t,
                const float* __restrict__ item_embed,
                const float* __restrict__ g_tv,
                const float* __restrict__ nW1, const float* __restrict__ nb1,
                const float* __restrict__ nW2, const float* __restrict__ nb2,
                const float* __restrict__ aW1, const float* __restrict__ ab1,
                const float* __restrict__ aW2, const float* __restrict__ ab2,
                const float* __restrict__ oW1, const float* __restrict__ ob1,
                const float* __restrict__ oW2, const float* __restrict__ ob2,
                float* __restrict__ out) {
    const int tid = threadIdx.x, w = tid >> 5, lane = tid & 31;

    // ---- stage weights into B-fragment-packed smem (hi,hi,lo,lo per uint4) ----
    {
        const float* wsrc[8] = { nW1, nW2, aW1, aW1 + 4096, aW2, oW1, oW1 + 4096, oW2 };
#pragma unroll 1
        for (int e = tid; e < 8192; e += TPB) {
            const int t = e >> 10, rem = e & 1023, ktnt = rem >> 5, ln = rem & 31;
            const int k0 = (ktnt >> 3) * 16 + (ln & 3) * 2;
            const int n  = (ktnt & 7) * 8 + (ln >> 2);
            const float* s = wsrc[t];
            const float w00 = s[(k0)     * 64 + n], w01 = s[(k0 + 1) * 64 + n];
            const float w10 = s[(k0 + 8) * 64 + n], w11 = s[(k0 + 9) * 64 + n];
            u32 bh0, bl0, bh1, bl1;
            splitpk(make_float2(w00, w01), bh0, bl0);
            splitpk(make_float2(w10, w11), bh1, bl1);
            *(uint4*)(smc + OFF_W + (size_t)t * W_TILE + ((size_t)ktnt * 32 + ln) * 16) =
                make_uint4(bh0, bh1, bl0, bl1);
        }
        float* sb = (float*)(smc + OFF_BIAS);
        if (tid < 64) {
            sb[tid]       = nb1[tid]; sb[64 + tid]  = nb2[tid];
            sb[128 + tid] = ab1[tid]; sb[192 + tid] = ab2[tid];
            sb[256 + tid] = ob1[tid]; sb[320 + tid] = ob2[tid];
            ((float*)(smc + OFF_TV))[tid] = g_tv[tid];
        }
    }
    __syncthreads();

    const float* BS  = (const float*)(smc + OFF_BIAS);
    const float* tvs = (const float*)(smc + OFF_TV);
    float t2 = 0.f;
#pragma unroll
    for (int c = 0; c < 64; c++) t2 = fmaf(tvs[c], tvs[c], t2);
    const float tvd = fmaxf(sqrtf(t2), 1e-8f);

    // warp owns 16 rows: g0 = base + lane/4, and g0+8
    const int g0 = blockIdx.x * MROWS + w * 16 + (lane >> 2);
    const int q  = lane & 3;
    const int gA = min(g0, BATCHN - 1);          // clamped read rows
    const int gB = min(g0 + 8, BATCHN - 1);
    char* B0 = smc + OFF_A + w * 8192;
    char* B1 = B0 + 4096;

    u32 Xh[16], Xl[16];

#define EMB(id) (item_embed + (size_t)(id) * 64)

    gather_r(Xh, Xl, EMB(seq[gA * 5 + 1]), EMB(seq[gB * 5 + 1]), q);   // e(seq1)
    not_r(Xh, Xl, B0, BS + 0, lane);                                   // n1 -> B0
    gather_r(Xh, Xl, EMB(seq[gA * 5 + 0]), EMB(seq[gB * 5 + 0]), q);   // e(seq0)
    mlp2_rs(Xh, Xl, B0, WT(2), BS + 128, lane);                        // int5 = AND(e0,n1) -> B0
    gather_r(Xh, Xl, EMB(seq[gA * 5 + 2]), EMB(seq[gB * 5 + 2]), q);   // e(seq2)
    st_buf(B1, Xh, Xl, lane);                                          // e2 -> B1
    gather_r(Xh, Xl, EMB(seq[gA * 5 + 3]), EMB(seq[gB * 5 + 3]), q);   // e(seq3)
    mlp2_sr(B1, Xh, Xl, WT(5), BS + 256, lane);                        // int6 = OR(e2,e3) -> B1
    mlp2_ss(B0, B1, WT(2), BS + 128, lane);                            // int7 = AND(int5,int6) -> B0
    not_s(B0, BS + 0, lane);                                           // n7 -> B0
    gather_r(Xh, Xl, EMB(seq[gA * 5 + 4]), EMB(seq[gB * 5 + 4]), q);   // e(seq4)
    mlp2_sr(B0, Xh, Xl, WT(5), BS + 256, lane);                        // out = OR(n7,e4) -> B0
    not_s(B0, BS + 0, lane);                                           // enc_not -> B0
    gather_r(Xh, Xl, EMB(pos_t[gA]), EMB(pos_t[gB]), q);               // pos_e
    mlp2_cos(B0, Xh, Xl, WT(5), BS + 256, tvs, tvd, out, g0, lane);
    gather_r(Xh, Xl, EMB(neg_t[gA]), EMB(neg_t[gB]), q);               // neg_e
    mlp2_cos(B0, Xh, Xl, WT(5), BS + 256, tvs, tvd, out + BATCHN, g0, lane);
}

extern "C" void kernel_launch(void* const* d_in, const int* in_sizes, int n_in,
                              void* d_out, int out_size) {
    (void)in_sizes; (void)n_in; (void)out_size;
    cudaFuncSetAttribute(logicnet_kernel,
                         cudaFuncAttributeMaxDynamicSharedMemorySize, SMEM_BYTES);
    logicnet_kernel<<<NBLOCKS, TPB, SMEM_BYTES>>>(
        (const int*)d_in[0], (const int*)d_in[1], (const int*)d_in[2],
        (const float*)d_in[3], (const float*)d_in[4],
        (const float*)d_in[5], (const float*)d_in[6],
        (const float*)d_in[7], (const float*)d_in[8],
        (const float*)d_in[9], (const float*)d_in[10],
        (const float*)d_in[11], (const float*)d_in[12],
        (const float*)d_in[13], (const float*)d_in[14],
        (const float*)d_in[15], (const float*)d_in[16],
        (float*)d_out);
}

// round 12
// speedup vs baseline: 1.4661x; 1.1163x over previous
#include <cuda_runtime.h>
#include <cuda_bf16.h>
#include <cstdint>

typedef uint32_t u32;

#define BATCHN 131072
#define WARPS  12
#define TPB    (WARPS * 32)
#define MROWS  (WARPS * 16)                      // 192 rows per CTA
#define NBLOCKS ((BATCHN + MROWS - 1) / MROWS)   // 683

// smem byte layout
#define OFF_W    0                // 8 weight tiles, B-frag packed, 16KB each
#define W_TILE   16384
#define OFF_A    131072           // 12 warps x 2 buffers x 4KB (hi 2K + lo 2K)
#define OFF_BIAS 229376           // 6 x 64 fp32
#define OFF_TV   230912           // 64 fp32
#define SMEM_BYTES 231168

extern __shared__ char smc[];

static __device__ __forceinline__ void mma_bf16(float* c, const u32* a, u32 b0, u32 b1) {
    asm volatile("mma.sync.aligned.m16n8k16.row.col.f32.bf16.bf16.f32 "
        "{%0,%1,%2,%3},{%4,%5,%6,%7},{%8,%9},{%0,%1,%2,%3};"
        : "+f"(c[0]), "+f"(c[1]), "+f"(c[2]), "+f"(c[3])
        : "r"(a[0]), "r"(a[1]), "r"(a[2]), "r"(a[3]), "r"(b0), "r"(b1));
}

// fast fp32x2 -> packed bf16 hi + packed bf16 lo (RN hi, exact residual, RN lo)
static __device__ __forceinline__ void splitpk(float2 v, u32& hp, u32& lp) {
    u32 h;
    asm("cvt.rn.bf16x2.f32 %0, %1, %2;" : "=r"(h) : "f"(v.y), "f"(v.x));
    const float h0 = __uint_as_float(h << 16);
    const float h1 = __uint_as_float(h & 0xFFFF0000u);
    const float l0 = v.x - h0;
    const float l1 = v.y - h1;
    asm("cvt.rn.bf16x2.f32 %0, %1, %2;" : "=r"(lp) : "f"(l1), "f"(l0));
    hp = h;
}
static __device__ __forceinline__ float lrelu(float v) {
    return v > 0.f ? v : 0.01f * v;
}
static __device__ __forceinline__ void zeroC(float* C) {
#pragma unroll
    for (int i = 0; i < 32; i++) C[i] = 0.f;
}

// ---- GEMM unit (64x64, 3-pass bf16 emulation), A from smem buffer ----
static __device__ __forceinline__ void gemm_s(float C[32], const char* ab,
                                              const char* wt, int lane) {
#pragma unroll 2
    for (int kt = 0; kt < 4; kt++) {
        const uint4 Ah = *(const uint4*)(ab + ((kt * 32 + lane) << 4));
        const uint4 Al = *(const uint4*)(ab + 2048 + ((kt * 32 + lane) << 4));
#pragma unroll
        for (int nt = 0; nt < 8; nt++) {
            const uint4 B = *(const uint4*)(wt + (((kt * 8 + nt) * 32 + lane) << 4));
            mma_bf16(C + nt * 4, (const u32*)&Ah, B.x, B.y);
            mma_bf16(C + nt * 4, (const u32*)&Ah, B.z, B.w);
            mma_bf16(C + nt * 4, (const u32*)&Al, B.x, B.y);
        }
    }
}
// ---- GEMM unit, A from registers ----
static __device__ __forceinline__ void gemm_r(float C[32], const u32* Hh, const u32* Hl,
                                              const char* wt, int lane) {
#pragma unroll 2
    for (int kt = 0; kt < 4; kt++) {
#pragma unroll
        for (int nt = 0; nt < 8; nt++) {
            const uint4 B = *(const uint4*)(wt + (((kt * 8 + nt) * 32 + lane) << 4));
            mma_bf16(C + nt * 4, Hh + 4 * kt, B.x, B.y);
            mma_bf16(C + nt * 4, Hh + 4 * kt, B.z, B.w);
            mma_bf16(C + nt * 4, Hl + 4 * kt, B.x, B.y);
        }
    }
}

// ---- C (+bias, opt lrelu) -> A-fragment registers ----
static __device__ __forceinline__ void epi_r(const float C[32], const float* bias,
                                             bool relu, u32* Hh, u32* Hl, int lane) {
    const int cb = (lane & 3) * 2;
#pragma unroll
    for (int nt = 0; nt < 8; nt++) {
        const float bb0 = bias[8 * nt + cb], bb1 = bias[8 * nt + cb + 1];
        float v0 = C[nt * 4 + 0] + bb0, v1 = C[nt * 4 + 1] + bb1;
        float v2 = C[nt * 4 + 2] + bb0, v3 = C[nt * 4 + 3] + bb1;
        if (relu) { v0 = lrelu(v0); v1 = lrelu(v1); v2 = lrelu(v2); v3 = lrelu(v3); }
        const int o = (nt >> 1) * 4 + (nt & 1) * 2;
        splitpk(make_float2(v0, v1), Hh[o], Hl[o]);
        splitpk(make_float2(v2, v3), Hh[o + 1], Hl[o + 1]);
    }
}
// ---- A-frag regs -> smem buffer (lane-private) ----
static __device__ __forceinline__ void st_buf(char* dst, const u32* Hh, const u32* Hl,
                                              int lane) {
#pragma unroll
    for (int kt = 0; kt < 4; kt++) {
        *(uint4*)(dst + ((kt * 32 + lane) << 4)) =
            make_uint4(Hh[4 * kt], Hh[4 * kt + 1], Hh[4 * kt + 2], Hh[4 * kt + 3]);
        *(uint4*)(dst + 2048 + ((kt * 32 + lane) << 4)) =
            make_uint4(Hl[4 * kt], Hl[4 * kt + 1], Hl[4 * kt + 2], Hl[4 * kt + 3]);
    }
}
// ---- gather 2 embedding rows -> A-frag registers ----
static __device__ __forceinline__ void gather_r(u32* Hh, u32* Hl, const float* e0,
                                                const float* e1, int q) {
#pragma unroll
    for (int kt = 0; kt < 4; kt++) {
        float2 a = ((const float2*)e0)[8 * kt + q];
        float2 b = ((const float2*)e1)[8 * kt + q];
        float2 c = ((const float2*)e0)[8 * kt + q + 4];
        float2 d = ((const float2*)e1)[8 * kt + q + 4];
        splitpk(a, Hh[4 * kt + 0], Hl[4 * kt + 0]);
        splitpk(b, Hh[4 * kt + 1], Hl[4 * kt + 1]);
        splitpk(c, Hh[4 * kt + 2], Hl[4 * kt + 2]);
        splitpk(d, Hh[4 * kt + 3], Hl[4 * kt + 3]);
    }
}

#define WT(i) (smc + OFF_W + (i) * W_TILE)

// NOT from smem buf, in place (all reads precede lane-private writes)
static __device__ __forceinline__ void not_s(char* buf, const float* bs, int lane) {
    float C[32]; u32 Hh[16], Hl[16];
    zeroC(C); gemm_s(C, buf, WT(0), lane);
    epi_r(C, bs, true, Hh, Hl, lane);
    zeroC(C); gemm_r(C, Hh, Hl, WT(1), lane);
    epi_r(C, bs + 64, false, Hh, Hl, lane);
    st_buf(buf, Hh, Hl, lane);
}
// NOT from reg X -> buf
static __device__ __forceinline__ void not_r(const u32* Xh, const u32* Xl, char* buf,
                                             const float* bs, int lane) {
    float C[32]; u32 Hh[16], Hl[16];
    zeroC(C); gemm_r(C, Xh, Xl, WT(0), lane);
    epi_r(C, bs, true, Hh, Hl, lane);
    zeroC(C); gemm_r(C, Hh, Hl, WT(1), lane);
    epi_r(C, bs + 64, false, Hh, Hl, lane);
    st_buf(buf, Hh, Hl, lane);
}
// x1 = regs (@W1a), x2 = smem buf (@W1b); result -> buf
static __device__ __forceinline__ void mlp2_rs(const u32* Xh, const u32* Xl, char* buf,
                                               const char* ta, const float* bs, int lane) {
    float C[32]; u32 Hh[16], Hl[16];
    zeroC(C);
    gemm_r(C, Xh, Xl, ta, lane);
    gemm_s(C, buf, ta + W_TILE, lane);
    epi_r(C, bs, true, Hh, Hl, lane);
    zeroC(C); gemm_r(C, Hh, Hl, ta + 2 * W_TILE, lane);
    epi_r(C, bs + 64, false, Hh, Hl, lane);
    st_buf(buf, Hh, Hl, lane);
}
// x1 = smem buf (@W1a), x2 = regs (@W1b); result -> buf
static __device__ __forceinline__ void mlp2_sr(char* buf, const u32* Xh, const u32* Xl,
                                               const char* ta, const float* bs, int lane) {
    float C[32]; u32 Hh[16], Hl[16];
    zeroC(C);
    gemm_s(C, buf, ta, lane);
    gemm_r(C, Xh, Xl, ta + W_TILE, lane);
    epi_r(C, bs, true, Hh, Hl, lane);
    zeroC(C); gemm_r(C, Hh, Hl, ta + 2 * W_TILE, lane);
    epi_r(C, bs + 64, false, Hh, Hl, lane);
    st_buf(buf, Hh, Hl, lane);
}
// both smem; result -> x1
static __device__ __forceinline__ void mlp2_ss(char* x1, char* x2, const char* ta,
                                               const float* bs, int lane) {
    float C[32]; u32 Hh[16], Hl[16];
    zeroC(C);
    gemm_s(C, x1, ta, lane);
    gemm_s(C, x2, ta + W_TILE, lane);
    epi_r(C, bs, true, Hh, Hl, lane);
    zeroC(C); gemm_r(C, Hh, Hl, ta + 2 * W_TILE, lane);
    epi_r(C, bs + 64, false, Hh, Hl, lane);
    st_buf(x1, Hh, Hl, lane);
}
// x1 smem (PRESERVED) @W1a, x2 regs @W1b; cosine epilogue -> out
static __device__ __forceinline__ void mlp2_cos(char* x1, const u32* Xh, const u32* Xl,
                                                const char* ta, const float* bs,
                                                const float* tvs, float tvd,
                                                float* outp, int g0, int lane) {
    float C[32]; u32 Hh[16], Hl[16];
    zeroC(C);
    gemm_s(C, x1, ta, lane);
    gemm_r(C, Xh, Xl, ta + W_TILE, lane);
    epi_r(C, bs, true, Hh, Hl, lane);
    zeroC(C); gemm_r(C, Hh, Hl, ta + 2 * W_TILE, lane);

    const float* b2 = bs + 64;
    const int cb = (lane & 3) * 2;
    float nu0 = 0.f, nr0 = 0.f, nu1 = 0.f, nr1 = 0.f;
#pragma unroll
    for (int nt = 0; nt < 8; nt++) {
        const int c0 = 8 * nt + cb;
        const float bb0 = b2[c0], bb1 = b2[c0 + 1];
        const float t0 = tvs[c0], t1 = tvs[c0 + 1];
        float v0 = C[nt * 4 + 0] + bb0, v1 = C[nt * 4 + 1] + bb1;
        float v2 = C[nt * 4 + 2] + bb0, v3 = C[nt * 4 + 3] + bb1;
        nu0 = fmaf(v0, t0, fmaf(v1, t1, nu0));
        nr0 = fmaf(v0, v0, fmaf(v1, v1, nr0));
        nu1 = fmaf(v2, t0, fmaf(v3, t1, nu1));
        nr1 = fmaf(v2, v2, fmaf(v3, v3, nr1));
    }
#pragma unroll
    for (int off = 1; off <= 2; off <<= 1) {
        nu0 += __shfl_xor_sync(~0u, nu0, off);
        nr0 += __shfl_xor_sync(~0u, nr0, off);
        nu1 += __shfl_xor_sync(~0u, nu1, off);
        nr1 += __shfl_xor_sync(~0u, nr1, off);
    }
    if ((lane & 3) == 0) {
        if (g0 < BATCHN)
            outp[g0]     = nu0 / (fmaxf(sqrtf(nr0), 1e-8f) * tvd) * 10.0f;
        if (g0 + 8 < BATCHN)
            outp[g0 + 8] = nu1 / (fmaxf(sqrtf(nr1), 1e-8f) * tvd) * 10.0f;
    }
}

__global__ void __launch_bounds__(TPB, 1)
logicnet_kernel(const int* __restrict__ seq,
                const int* __restrict__ pos_t,
                const int* __restrict__ neg_t,
                const float* __restrict__ item_embed,
                const float* __restrict__ g_tv,
                const float* __restrict__ nW1, const float* __restrict__ nb1,
                const float* __restrict__ nW2, const float* __restrict__ nb2,
                const float* __restrict__ aW1, const float* __restrict__ ab1,
                const float* __restrict__ aW2, const float* __restrict__ ab2,
                const float* __restrict__ oW1, const float* __restrict__ ob1,
                const float* __restrict__ oW2, const float* __restrict__ ob2,
                float* __restrict__ out) {
    const int tid = threadIdx.x, w = tid >> 5, lane = tid & 31;

    // ---- stage weights into B-fragment-packed smem (hi,hi,lo,lo per uint4) ----
    {
        const float* wsrc[8] = { nW1, nW2, aW1, aW1 + 4096, aW2, oW1, oW1 + 4096, oW2 };
#pragma unroll 1
        for (int e = tid; e < 8192; e += TPB) {
            const int t = e >> 10, rem = e & 1023, ktnt = rem >> 5, ln = rem & 31;
            const int k0 = (ktnt >> 3) * 16 + (ln & 3) * 2;
            const int n  = (ktnt & 7) * 8 + (ln >> 2);
            const float* s = wsrc[t];
            const float w00 = s[(k0)     * 64 + n], w01 = s[(k0 + 1) * 64 + n];
            const float w10 = s[(k0 + 8) * 64 + n], w11 = s[(k0 + 9) * 64 + n];
            u32 bh0, bl0, bh1, bl1;
            splitpk(make_float2(w00, w01), bh0, bl0);
            splitpk(make_float2(w10, w11), bh1, bl1);
            *(uint4*)(smc + OFF_W + (size_t)t * W_TILE + ((size_t)ktnt * 32 + ln) * 16) =
                make_uint4(bh0, bh1, bl0, bl1);
        }
        float* sb = (float*)(smc + OFF_BIAS);
        if (tid < 64) {
            sb[tid]       = nb1[tid]; sb[64 + tid]  = nb2[tid];
            sb[128 + tid] = ab1[tid]; sb[192 + tid] = ab2[tid];
            sb[256 + tid] = ob1[tid]; sb[320 + tid] = ob2[tid];
            ((float*)(smc + OFF_TV))[tid] = g_tv[tid];
        }
    }
    __syncthreads();

    const float* BS  = (const float*)(smc + OFF_BIAS);
    const float* tvs = (const float*)(smc + OFF_TV);
    float t2 = 0.f;
#pragma unroll
    for (int c = 0; c < 64; c++) t2 = fmaf(tvs[c], tvs[c], t2);
    const float tvd = fmaxf(sqrtf(t2), 1e-8f);

    // warp owns 16 rows: g0 = base + lane/4, and g0+8
    const int g0 = blockIdx.x * MROWS + w * 16 + (lane >> 2);
    const int q  = lane & 3;
    const int gA = min(g0, BATCHN - 1);          // clamped read rows
    const int gB = min(g0 + 8, BATCHN - 1);
    char* B0 = smc + OFF_A + w * 8192;
    char* B1 = B0 + 4096;

    u32 Xh[16], Xl[16];

#define EMB(id) (item_embed + (size_t)(id) * 64)

    gather_r(Xh, Xl, EMB(seq[gA * 5 + 1]), EMB(seq[gB * 5 + 1]), q);   // e(seq1)
    not_r(Xh, Xl, B0, BS + 0, lane);                                   // n1 -> B0
    gather_r(Xh, Xl, EMB(seq[gA * 5 + 0]), EMB(seq[gB * 5 + 0]), q);   // e(seq0)
    mlp2_rs(Xh, Xl, B0, WT(2), BS + 128, lane);                        // int5 = AND(e0,n1) -> B0
    gather_r(Xh, Xl, EMB(seq[gA * 5 + 2]), EMB(seq[gB * 5 + 2]), q);   // e(seq2)
    st_buf(B1, Xh, Xl, lane);                                          // e2 -> B1
    gather_r(Xh, Xl, EMB(seq[gA * 5 + 3]), EMB(seq[gB * 5 + 3]), q);   // e(seq3)
    mlp2_sr(B1, Xh, Xl, WT(5), BS + 256, lane);                        // int6 = OR(e2,e3) -> B1
    mlp2_ss(B0, B1, WT(2), BS + 128, lane);                            // int7 = AND(int5,int6) -> B0
    not_s(B0, BS + 0, lane);                                           // n7 -> B0
    gather_r(Xh, Xl, EMB(seq[gA * 5 + 4]), EMB(seq[gB * 5 + 4]), q);   // e(seq4)
    mlp2_sr(B0, Xh, Xl, WT(5), BS + 256, lane);                        // out = OR(n7,e4) -> B0
    not_s(B0, BS + 0, lane);                                           // enc_not -> B0
    gather_r(Xh, Xl, EMB(pos_t[gA]), EMB(pos_t[gB]), q);               // pos_e
    mlp2_cos(B0, Xh, Xl, WT(5), BS + 256, tvs, tvd, out, g0, lane);
    gather_r(Xh, Xl, EMB(neg_t[gA]), EMB(neg_t[gB]), q);               // neg_e
    mlp2_cos(B0, Xh, Xl, WT(5), BS + 256, tvs, tvd, out + BATCHN, g0, lane);
}

extern "C" void kernel_launch(void* const* d_in, const int* in_sizes, int n_in,
                              void* d_out, int out_size) {
    (void)in_sizes; (void)n_in; (void)out_size;
    cudaFuncSetAttribute(logicnet_kernel,
                         cudaFuncAttributeMaxDynamicSharedMemorySize, SMEM_BYTES);
    logicnet_kernel<<<NBLOCKS, TPB, SMEM_BYTES>>>(
        (const int*)d_in[0], (const int*)d_in[1], (const int*)d_in[2],
        (const float*)d_in[3], (const float*)d_in[4],
        (const float*)d_in[5], (const float*)d_in[6],
        (const float*)d_in[7], (const float*)d_in[8],
        (const float*)d_in[9], (const float*)d_in[10],
        (const float*)d_in[11], (const float*)d_in[12],
        (const float*)d_in[13], (const float*)d_in[14],
        (const float*)d_in[15], (const float*)d_in[16],
        (float*)d_out);
}

// round 13
// speedup vs baseline: 1.9494x; 1.3296x over previous
#include <cuda_runtime.h>
#include <cuda_fp16.h>
#include <cstdint>

typedef uint32_t u32;

#define BATCHN 131072
#define WARPS  14
#define TPB    (WARPS * 32)
#define MROWS  (WARPS * 16)                      // 224 rows per CTA
#define NBLOCKS ((BATCHN + MROWS - 1) / MROWS)   // 586

#define SSCALE 256.0f
#define INVS   (1.0f / 256.0f)

// smem byte layout
#define OFF_W    0                // 8 weight tiles (fp16 hi-only, nt-paired), 8KB each
#define W_TILE   8192
#define OFF_A    65536            // 14 warps x 2 buffers x 4KB (hi 2K + lo 2K)
#define OFF_BIAS 180224           // 6 x 64 fp32 (pre-scaled x256)
#define OFF_TV   181760           // 64 fp32
#define SMEM_BYTES 182016

extern __shared__ char smc[];

static __device__ __forceinline__ void mma_f16(float* c, const u32* a, u32 b0, u32 b1) {
    asm volatile("mma.sync.aligned.m16n8k16.row.col.f32.f16.f16.f32 "
        "{%0,%1,%2,%3},{%4,%5,%6,%7},{%8,%9},{%0,%1,%2,%3};"
        : "+f"(c[0]), "+f"(c[1]), "+f"(c[2]), "+f"(c[3])
        : "r"(a[0]), "r"(a[1]), "r"(a[2]), "r"(a[3]), "r"(b0), "r"(b1));
}

static __device__ __forceinline__ u32 pkf16(float a, float b) {
    __half2 t = __floats2half2_rn(a, b);
    return *reinterpret_cast<u32*>(&t);
}
// fp32x2 (already in scaled domain) -> packed f16 hi + packed f16 lo residual
static __device__ __forceinline__ void splitpk(float2 v, u32& hp, u32& lp) {
    __half2 h2 = __floats2half2_rn(v.x, v.y);
    hp = *reinterpret_cast<u32*>(&h2);
    float2 hf = __half22float2(h2);
    lp = pkf16(v.x - hf.x, v.y - hf.y);
}
static __device__ __forceinline__ float lrelu(float v) {
    return v > 0.f ? v : 0.01f * v;
}
static __device__ __forceinline__ void zeroC(float* C) {
#pragma unroll
    for (int i = 0; i < 32; i++) C[i] = 0.f;
}

// ---- GEMM unit (64x64): C += (Ah+Al) @ Wh, A from smem buffer ----
static __device__ __forceinline__ void gemm_s(float C[32], const char* ab,
                                              const char* wt, int lane) {
#pragma unroll 2
    for (int kt = 0; kt < 4; kt++) {
        const uint4 Ah = *(const uint4*)(ab + ((kt * 32 + lane) << 4));
        const uint4 Al = *(const uint4*)(ab + 2048 + ((kt * 32 + lane) << 4));
#pragma unroll
        for (int np = 0; np < 4; np++) {
            const uint4 B = *(const uint4*)(wt + (((kt * 4 + np) * 32 + lane) << 4));
            mma_f16(C + (2 * np) * 4,     (const u32*)&Ah, B.x, B.y);
            mma_f16(C + (2 * np) * 4,     (const u32*)&Al, B.x, B.y);
            mma_f16(C + (2 * np + 1) * 4, (const u32*)&Ah, B.z, B.w);
            mma_f16(C + (2 * np + 1) * 4, (const u32*)&Al, B.z, B.w);
        }
    }
}
// ---- GEMM unit, A from registers ----
static __device__ __forceinline__ void gemm_r(float C[32], const u32* Hh, const u32* Hl,
                                              const char* wt, int lane) {
#pragma unroll 2
    for (int kt = 0; kt < 4; kt++) {
#pragma unroll
        for (int np = 0; np < 4; np++) {
            const uint4 B = *(const uint4*)(wt + (((kt * 4 + np) * 32 + lane) << 4));
            mma_f16(C + (2 * np) * 4,     Hh + 4 * kt, B.x, B.y);
            mma_f16(C + (2 * np) * 4,     Hl + 4 * kt, B.x, B.y);
            mma_f16(C + (2 * np + 1) * 4, Hh + 4 * kt, B.z, B.w);
            mma_f16(C + (2 * np + 1) * 4, Hl + 4 * kt, B.z, B.w);
        }
    }
}

// ---- C (x 1/256, +scaled bias, opt lrelu) -> A-fragment registers ----
static __device__ __forceinline__ void epi_r(const float C[32], const float* bias,
                                             bool relu, u32* Hh, u32* Hl, int lane) {
    const int cb = (lane & 3) * 2;
#pragma unroll
    for (int nt = 0; nt < 8; nt++) {
        const float bb0 = bias[8 * nt + cb], bb1 = bias[8 * nt + cb + 1];
        float v0 = fmaf(C[nt * 4 + 0], INVS, bb0), v1 = fmaf(C[nt * 4 + 1], INVS, bb1);
        float v2 = fmaf(C[nt * 4 + 2], INVS, bb0), v3 = fmaf(C[nt * 4 + 3], INVS, bb1);
        if (relu) { v0 = lrelu(v0); v1 = lrelu(v1); v2 = lrelu(v2); v3 = lrelu(v3); }
        const int o = (nt >> 1) * 4 + (nt & 1) * 2;
        splitpk(make_float2(v0, v1), Hh[o], Hl[o]);
        splitpk(make_float2(v2, v3), Hh[o + 1], Hl[o + 1]);
    }
}
// ---- A-frag regs -> smem buffer (lane-private) ----
static __device__ __forceinline__ void st_buf(char* dst, const u32* Hh, const u32* Hl,
                                              int lane) {
#pragma unroll
    for (int kt = 0; kt < 4; kt++) {
        *(uint4*)(dst + ((kt * 32 + lane) << 4)) =
            make_uint4(Hh[4 * kt], Hh[4 * kt + 1], Hh[4 * kt + 2], Hh[4 * kt + 3]);
        *(uint4*)(dst + 2048 + ((kt * 32 + lane) << 4)) =
            make_uint4(Hl[4 * kt], Hl[4 * kt + 1], Hl[4 * kt + 2], Hl[4 * kt + 3]);
    }
}
// ---- gather 2 embedding rows (x256) -> A-frag registers ----
static __device__ __forceinline__ void gather_r(u32* Hh, u32* Hl, const float* e0,
                                                const float* e1, int q) {
#pragma unroll
    for (int kt = 0; kt < 4; kt++) {
        float2 a = ((const float2*)e0)[8 * kt + q];
        float2 b = ((const float2*)e1)[8 * kt + q];
        float2 c = ((const float2*)e0)[8 * kt + q + 4];
        float2 d = ((const float2*)e1)[8 * kt + q + 4];
        splitpk(make_float2(a.x * SSCALE, a.y * SSCALE), Hh[4 * kt + 0], Hl[4 * kt + 0]);
        splitpk(make_float2(b.x * SSCALE, b.y * SSCALE), Hh[4 * kt + 1], Hl[4 * kt + 1]);
        splitpk(make_float2(c.x * SSCALE, c.y * SSCALE), Hh[4 * kt + 2], Hl[4 * kt + 2]);
        splitpk(make_float2(d.x * SSCALE, d.y * SSCALE), Hh[4 * kt + 3], Hl[4 * kt + 3]);
    }
}

#define WT(i) (smc + OFF_W + (i) * W_TILE)

// NOT from smem buf, in place (all reads precede lane-private writes)
static __device__ __forceinline__ void not_s(char* buf, const float* bs, int lane) {
    float C[32]; u32 Hh[16], Hl[16];
    zeroC(C); gemm_s(C, buf, WT(0), lane);
    epi_r(C, bs, true, Hh, Hl, lane);
    zeroC(C); gemm_r(C, Hh, Hl, WT(1), lane);
    epi_r(C, bs + 64, false, Hh, Hl, lane);
    st_buf(buf, Hh, Hl, lane);
}
// NOT from reg X -> buf
static __device__ __forceinline__ void not_r(const u32* Xh, const u32* Xl, char* buf,
                                             const float* bs, int lane) {
    float C[32]; u32 Hh[16], Hl[16];
    zeroC(C); gemm_r(C, Xh, Xl, WT(0), lane);
    epi_r(C, bs, true, Hh, Hl, lane);
    zeroC(C); gemm_r(C, Hh, Hl, WT(1), lane);
    epi_r(C, bs + 64, false, Hh, Hl, lane);
    st_buf(buf, Hh, Hl, lane);
}
// x1 = regs (@W1a), x2 = smem buf (@W1b); result -> buf
static __device__ __forceinline__ void mlp2_rs(const u32* Xh, const u32* Xl, char* buf,
                                               const char* ta, const float* bs, int lane) {
    float C[32]; u32 Hh[16], Hl[16];
    zeroC(C);
    gemm_r(C, Xh, Xl, ta, lane);
    gemm_s(C, buf, ta + W_TILE, lane);
    epi_r(C, bs, true, Hh, Hl, lane);
    zeroC(C); gemm_r(C, Hh, Hl, ta + 2 * W_TILE, lane);
    epi_r(C, bs + 64, false, Hh, Hl, lane);
    st_buf(buf, Hh, Hl, lane);
}
// x1 = smem buf (@W1a), x2 = regs (@W1b); result -> buf
static __device__ __forceinline__ void mlp2_sr(char* buf, const u32* Xh, const u32* Xl,
                                               const char* ta, const float* bs, int lane) {
    float C[32]; u32 Hh[16], Hl[16];
    zeroC(C);
    gemm_s(C, buf, ta, lane);
    gemm_r(C, Xh, Xl, ta + W_TILE, lane);
    epi_r(C, bs, true, Hh, Hl, lane);
    zeroC(C); gemm_r(C, Hh, Hl, ta + 2 * W_TILE, lane);
    epi_r(C, bs + 64, false, Hh, Hl, lane);
    st_buf(buf, Hh, Hl, lane);
}
// both smem; result -> x1
static __device__ __forceinline__ void mlp2_ss(char* x1, char* x2, const char* ta,
                                               const float* bs, int lane) {
    float C[32]; u32 Hh[16], Hl[16];
    zeroC(C);
    gemm_s(C, x1, ta, lane);
    gemm_s(C, x2, ta + W_TILE, lane);
    epi_r(C, bs, true, Hh, Hl, lane);
    zeroC(C); gemm_r(C, Hh, Hl, ta + 2 * W_TILE, lane);
    epi_r(C, bs + 64, false, Hh, Hl, lane);
    st_buf(x1, Hh, Hl, lane);
}
// x1 smem (PRESERVED) @W1a, x2 regs @W1b; cosine epilogue -> out
static __device__ __forceinline__ void mlp2_cos(char* x1, const u32* Xh, const u32* Xl,
                                                const char* ta, const float* bs,
                                                const float* tvs, float tvd,
                                                float* outp, int g0, int lane) {
    float C[32]; u32 Hh[16], Hl[16];
    zeroC(C);
    gemm_s(C, x1, ta, lane);
    gemm_r(C, Xh, Xl, ta + W_TILE, lane);
    epi_r(C, bs, true, Hh, Hl, lane);
    zeroC(C); gemm_r(C, Hh, Hl, ta + 2 * W_TILE, lane);

    // v = C/256 + 256*b2 = 256*encoded; cosine is scale-invariant
    const float* b2 = bs + 64;
    const int cb = (lane & 3) * 2;
    float nu0 = 0.f, nr0 = 0.f, nu1 = 0.f, nr1 = 0.f;
#pragma unroll
    for (int nt = 0; nt < 8; nt++) {
        const int c0 = 8 * nt + cb;
        const float bb0 = b2[c0], bb1 = b2[c0 + 1];
        const float t0 = tvs[c0], t1 = tvs[c0 + 1];
        float v0 = fmaf(C[nt * 4 + 0], INVS, bb0), v1 = fmaf(C[nt * 4 + 1], INVS, bb1);
        float v2 = fmaf(C[nt * 4 + 2], INVS, bb0), v3 = fmaf(C[nt * 4 + 3], INVS, bb1);
        nu0 = fmaf(v0, t0, fmaf(v1, t1, nu0));
        nr0 = fmaf(v0, v0, fmaf(v1, v1, nr0));
        nu1 = fmaf(v2, t0, fmaf(v3, t1, nu1));
        nr1 = fmaf(v2, v2, fmaf(v3, v3, nr1));
    }
#pragma unroll
    for (int off = 1; off <= 2; off <<= 1) {
        nu0 += __shfl_xor_sync(~0u, nu0, off);
        nr0 += __shfl_xor_sync(~0u, nr0, off);
        nu1 += __shfl_xor_sync(~0u, nu1, off);
        nr1 += __shfl_xor_sync(~0u, nr1, off);
    }
    if ((lane & 3) == 0) {
        if (g0 < BATCHN)
            outp[g0]     = nu0 / (fmaxf(sqrtf(nr0), 1e-8f) * tvd) * 10.0f;
        if (g0 + 8 < BATCHN)
            outp[g0 + 8] = nu1 / (fmaxf(sqrtf(nr1), 1e-8f) * tvd) * 10.0f;
    }
}

__global__ void __launch_bounds__(TPB, 1)
logicnet_kernel(const int* __restrict__ seq,
                const int* __restrict__ pos_t,
                const int* __restrict__ neg_t,
                const float* __restrict__ item_embed,
                const float* __restrict__ g_tv,
                const float* __restrict__ nW1, const float* __restrict__ nb1,
                const float* __restrict__ nW2, const float* __restrict__ nb2,
                const float* __restrict__ aW1, const float* __restrict__ ab1,
                const float* __restrict__ aW2, const float* __restrict__ ab2,
                const float* __restrict__ oW1, const float* __restrict__ ob1,
                const float* __restrict__ oW2, const float* __restrict__ ob2,
                float* __restrict__ out) {
    const int tid = threadIdx.x, w = tid >> 5, lane = tid & 31;

    // ---- stage weights (x256, fp16 hi-only) nt-paired: uint4 = {na.b0,na.b1,nb.b0,nb.b1} ----
    {
        const float* wsrc[8] = { nW1, nW2, aW1, aW1 + 4096, aW2, oW1, oW1 + 4096, oW2 };
#pragma unroll 1
        for (int e = tid; e < 4096; e += TPB) {
            const int t = e >> 9, rem = e & 511, ktnp = rem >> 5, ln = rem & 31;
            const int k0 = (ktnp >> 2) * 16 + (ln & 3) * 2;
            const int na = (ktnp & 3) * 16 + (ln >> 2);
            const int nb = na + 8;
            const float* s = wsrc[t];
            const u32 a0 = pkf16(s[(k0)     * 64 + na] * SSCALE, s[(k0 + 1) * 64 + na] * SSCALE);
            const u32 a1 = pkf16(s[(k0 + 8) * 64 + na] * SSCALE, s[(k0 + 9) * 64 + na] * SSCALE);
            const u32 b0 = pkf16(s[(k0)     * 64 + nb] * SSCALE, s[(k0 + 1) * 64 + nb] * SSCALE);
            const u32 b1 = pkf16(s[(k0 + 8) * 64 + nb] * SSCALE, s[(k0 + 9) * 64 + nb] * SSCALE);
            *(uint4*)(smc + OFF_W + (size_t)t * W_TILE + ((size_t)(ktnp * 32 + ln)) * 16) =
                make_uint4(a0, a1, b0, b1);
        }
        float* sb = (float*)(smc + OFF_BIAS);
        if (tid < 64) {
            sb[tid]       = nb1[tid] * SSCALE; sb[64 + tid]  = nb2[tid] * SSCALE;
            sb[128 + tid] = ab1[tid] * SSCALE; sb[192 + tid] = ab2[tid] * SSCALE;
            sb[256 + tid] = ob1[tid] * SSCALE; sb[320 + tid] = ob2[tid] * SSCALE;
            ((float*)(smc + OFF_TV))[tid] = g_tv[tid];
        }
    }
    __syncthreads();

    const float* BS  = (const float*)(smc + OFF_BIAS);
    const float* tvs = (const float*)(smc + OFF_TV);
    float t2 = 0.f;
#pragma unroll
    for (int c = 0; c < 64; c++) t2 = fmaf(tvs[c], tvs[c], t2);
    const float tvd = fmaxf(sqrtf(t2), 1e-8f);

    // warp owns 16 rows: g0 = base + lane/4, and g0+8
    const int g0 = blockIdx.x * MROWS + w * 16 + (lane >> 2);
    const int q  = lane & 3;
    const int gA = min(g0, BATCHN - 1);          // clamped read rows
    const int gB = min(g0 + 8, BATCHN - 1);
    char* B0 = smc + OFF_A + w * 8192;
    char* B1 = B0 + 4096;

    u32 Xh[16], Xl[16];

#define EMB(id) (item_embed + (size_t)(id) * 64)

    gather_r(Xh, Xl, EMB(seq[gA * 5 + 1]), EMB(seq[gB * 5 + 1]), q);   // e(seq1)
    not_r(Xh, Xl, B0, BS + 0, lane);                                   // n1 -> B0
    gather_r(Xh, Xl, EMB(seq[gA * 5 + 0]), EMB(seq[gB * 5 + 0]), q);   // e(seq0)
    mlp2_rs(Xh, Xl, B0, WT(2), BS + 128, lane);                        // int5 = AND(e0,n1) -> B0
    gather_r(Xh, Xl, EMB(seq[gA * 5 + 2]), EMB(seq[gB * 5 + 2]), q);   // e(seq2)
    st_buf(B1, Xh, Xl, lane);                                          // e2 -> B1
    gather_r(Xh, Xl, EMB(seq[gA * 5 + 3]), EMB(seq[gB * 5 + 3]), q);   // e(seq3)
    mlp2_sr(B1, Xh, Xl, WT(5), BS + 256, lane);                        // int6 = OR(e2,e3) -> B1
    mlp2_ss(B0, B1, WT(2), BS + 128, lane);                            // int7 = AND(int5,int6) -> B0
    not_s(B0, BS + 0, lane);                                           // n7 -> B0
    gather_r(Xh, Xl, EMB(seq[gA * 5 + 4]), EMB(seq[gB * 5 + 4]), q);   // e(seq4)
    mlp2_sr(B0, Xh, Xl, WT(5), BS + 256, lane);                        // out = OR(n7,e4) -> B0
    not_s(B0, BS + 0, lane);                                           // enc_not -> B0
    gather_r(Xh, Xl, EMB(pos_t[gA]), EMB(pos_t[gB]), q);               // pos_e
    mlp2_cos(B0, Xh, Xl, WT(5), BS + 256, tvs, tvd, out, g0, lane);
    gather_r(Xh, Xl, EMB(neg_t[gA]), EMB(neg_t[gB]), q);               // neg_e
    mlp2_cos(B0, Xh, Xl, WT(5), BS + 256, tvs, tvd, out + BATCHN, g0, lane);
}

extern "C" void kernel_launch(void* const* d_in, const int* in_sizes, int n_in,
                              void* d_out, int out_size) {
    (void)in_sizes; (void)n_in; (void)out_size;
    cudaFuncSetAttribute(logicnet_kernel,
                         cudaFuncAttributeMaxDynamicSharedMemorySize, SMEM_BYTES);
    logicnet_kernel<<<NBLOCKS, TPB, SMEM_BYTES>>>(
        (const int*)d_in[0], (const int*)d_in[1], (const int*)d_in[2],
        (const float*)d_in[3], (const float*)d_in[4],
        (const float*)d_in[5], (const float*)d_in[6],
        (const float*)d_in[7], (const float*)d_in[8],
        (const float*)d_in[9], (const float*)d_in[10],
        (const float*)d_in[11], (const float*)d_in[12],
        (const float*)d_in[13], (const float*)d_in[14],
        (const float*)d_in[15], (const float*)d_in[16],
        (float*)d_out);
}

// round 14
// speedup vs baseline: 3.3030x; 1.6944x over previous
#include <cuda_runtime.h>
#include <cuda_fp16.h>
#include <cstdint>

typedef uint32_t u32;

#define BATCHN 131072
#define WARPS  14
#define TPB    (WARPS * 32)
#define MROWS  (WARPS * 32)                      // 448 rows per CTA (32/warp)
#define NBLOCKS ((BATCHN + MROWS - 1) / MROWS)   // 293

#define SSCALE 256.0f
#define INVS   (1.0f / 256.0f)

// smem byte layout
#define OFF_W    0                // 8 weight tiles (fp16, nt-paired), 8KB each
#define W_TILE   8192
#define OFF_A    65536            // 14 warps x 2 buffers x 4KB (2 tiles x 2KB, hi-only)
#define OFF_BIAS 180224           // 6 x 64 fp32 (pre-scaled x256)
#define OFF_TV   181760           // 64 fp32
#define SMEM_BYTES 182016

extern __shared__ char smc[];

static __device__ __forceinline__ void mma_f16(float* c, const u32* a, u32 b0, u32 b1) {
    asm volatile("mma.sync.aligned.m16n8k16.row.col.f32.f16.f16.f32 "
        "{%0,%1,%2,%3},{%4,%5,%6,%7},{%8,%9},{%0,%1,%2,%3};"
        : "+f"(c[0]), "+f"(c[1]), "+f"(c[2]), "+f"(c[3])
        : "r"(a[0]), "r"(a[1]), "r"(a[2]), "r"(a[3]), "r"(b0), "r"(b1));
}

static __device__ __forceinline__ u32 pkf16(float a, float b) {
    __half2 t = __floats2half2_rn(a, b);
    return *reinterpret_cast<u32*>(&t);
}
static __device__ __forceinline__ float lrelu(float v) {
    return v > 0.f ? v : 0.01f * v;
}
static __device__ __forceinline__ void zeroC(float* C) {
#pragma unroll
    for (int i = 0; i < 32; i++) C[i] = 0.f;
}

// activation buffer: tile t (0/1), ktile kt, lane -> uint4 slot; 4KB per buffer
#define ABIX(kt, t, lane) ((((kt) * 2 + (t)) * 32 + (lane)) << 4)

// ---- GEMM unit (64x64, single-pass fp16), 2 M-tiles, A from smem ----
static __device__ __forceinline__ void gemm_s2(float C0[32], float C1[32],
                                               const char* ab, const char* wt, int lane) {
#pragma unroll 2
    for (int kt = 0; kt < 4; kt++) {
        const uint4 A0 = *(const uint4*)(ab + ABIX(kt, 0, lane));
        const uint4 A1 = *(const uint4*)(ab + ABIX(kt, 1, lane));
#pragma unroll
        for (int np = 0; np < 4; np++) {
            const uint4 B = *(const uint4*)(wt + (((kt * 4 + np) * 32 + lane) << 4));
            mma_f16(C0 + (2 * np) * 4,     (const u32*)&A0, B.x, B.y);
            mma_f16(C0 + (2 * np + 1) * 4, (const u32*)&A0, B.z, B.w);
            mma_f16(C1 + (2 * np) * 4,     (const u32*)&A1, B.x, B.y);
            mma_f16(C1 + (2 * np + 1) * 4, (const u32*)&A1, B.z, B.w);
        }
    }
}
// ---- GEMM unit, A from registers (X = 32 regs: tile0 16, tile1 16) ----
static __device__ __forceinline__ void gemm_r2(float C0[32], float C1[32],
                                               const u32* X, const char* wt, int lane) {
#pragma unroll 2
    for (int kt = 0; kt < 4; kt++) {
#pragma unroll
        for (int np = 0; np < 4; np++) {
            const uint4 B = *(const uint4*)(wt + (((kt * 4 + np) * 32 + lane) << 4));
            mma_f16(C0 + (2 * np) * 4,     X + 4 * kt, B.x, B.y);
            mma_f16(C0 + (2 * np + 1) * 4, X + 4 * kt, B.z, B.w);
            mma_f16(C1 + (2 * np) * 4,     X + 16 + 4 * kt, B.x, B.y);
            mma_f16(C1 + (2 * np + 1) * 4, X + 16 + 4 * kt, B.z, B.w);
        }
    }
}

// ---- one tile's C (x 1/256, +scaled bias, opt lrelu) -> 16 A-frag regs ----
static __device__ __forceinline__ void epi1(const float C[32], const float* bias,
                                            bool relu, u32* H, int lane) {
    const int cb = (lane & 3) * 2;
#pragma unroll
    for (int nt = 0; nt < 8; nt++) {
        const float bb0 = bias[8 * nt + cb], bb1 = bias[8 * nt + cb + 1];
        float v0 = fmaf(C[nt * 4 + 0], INVS, bb0), v1 = fmaf(C[nt * 4 + 1], INVS, bb1);
        float v2 = fmaf(C[nt * 4 + 2], INVS, bb0), v3 = fmaf(C[nt * 4 + 3], INVS, bb1);
        if (relu) { v0 = lrelu(v0); v1 = lrelu(v1); v2 = lrelu(v2); v3 = lrelu(v3); }
        const int o = (nt >> 1) * 4 + (nt & 1) * 2;
        H[o]     = pkf16(v0, v1);
        H[o + 1] = pkf16(v2, v3);
    }
}
// ---- 32 A-frag regs -> smem buffer (lane-private) ----
static __device__ __forceinline__ void st_buf2(char* dst, const u32* X, int lane) {
#pragma unroll
    for (int kt = 0; kt < 4; kt++) {
        *(uint4*)(dst + ABIX(kt, 0, lane)) =
            make_uint4(X[4 * kt], X[4 * kt + 1], X[4 * kt + 2], X[4 * kt + 3]);
        *(uint4*)(dst + ABIX(kt, 1, lane)) =
            make_uint4(X[16 + 4 * kt], X[17 + 4 * kt], X[18 + 4 * kt], X[19 + 4 * kt]);
    }
}
// ---- gather 4 embedding rows (x256, fp16) -> 32 A-frag regs ----
static __device__ __forceinline__ void gather_r2(u32* X, const float* e0, const float* e1,
                                                 const float* e2, const float* e3, int q) {
#pragma unroll
    for (int kt = 0; kt < 4; kt++) {
        float2 a = ((const float2*)e0)[8 * kt + q];
        float2 b = ((const float2*)e1)[8 * kt + q];
        float2 c = ((const float2*)e0)[8 * kt + q + 4];
        float2 d = ((const float2*)e1)[8 * kt + q + 4];
        X[4 * kt + 0] = pkf16(a.x * SSCALE, a.y * SSCALE);
        X[4 * kt + 1] = pkf16(b.x * SSCALE, b.y * SSCALE);
        X[4 * kt + 2] = pkf16(c.x * SSCALE, c.y * SSCALE);
        X[4 * kt + 3] = pkf16(d.x * SSCALE, d.y * SSCALE);
        float2 e = ((const float2*)e2)[8 * kt + q];
        float2 f = ((const float2*)e3)[8 * kt + q];
        float2 g = ((const float2*)e2)[8 * kt + q + 4];
        float2 h = ((const float2*)e3)[8 * kt + q + 4];
        X[16 + 4 * kt + 0] = pkf16(e.x * SSCALE, e.y * SSCALE);
        X[16 + 4 * kt + 1] = pkf16(f.x * SSCALE, f.y * SSCALE);
        X[16 + 4 * kt + 2] = pkf16(g.x * SSCALE, g.y * SSCALE);
        X[16 + 4 * kt + 3] = pkf16(h.x * SSCALE, h.y * SSCALE);
    }
}

#define WT(i) (smc + OFF_W + (i) * W_TILE)

// NOT from smem buf, in place
static __device__ __forceinline__ void not_s(char* buf, const float* bs, int lane) {
    float C0[32], C1[32]; u32 H[32];
    zeroC(C0); zeroC(C1);
    gemm_s2(C0, C1, buf, WT(0), lane);
    epi1(C0, bs, true, H, lane); epi1(C1, bs, true, H + 16, lane);
    zeroC(C0); zeroC(C1);
    gemm_r2(C0, C1, H, WT(1), lane);
    epi1(C0, bs + 64, false, H, lane); epi1(C1, bs + 64, false, H + 16, lane);
    st_buf2(buf, H, lane);
}
// NOT from reg X -> buf
static __device__ __forceinline__ void not_r(const u32* X, char* buf,
                                             const float* bs, int lane) {
    float C0[32], C1[32]; u32 H[32];
    zeroC(C0); zeroC(C1);
    gemm_r2(C0, C1, X, WT(0), lane);
    epi1(C0, bs, true, H, lane); epi1(C1, bs, true, H + 16, lane);
    zeroC(C0); zeroC(C1);
    gemm_r2(C0, C1, H, WT(1), lane);
    epi1(C0, bs + 64, false, H, lane); epi1(C1, bs + 64, false, H + 16, lane);
    st_buf2(buf, H, lane);
}
// x1 = regs (@W1a), x2 = smem (@W1b); result -> buf
static __device__ __forceinline__ void mlp2_rs(const u32* X, char* buf,
                                               const char* ta, const float* bs, int lane) {
    float C0[32], C1[32]; u32 H[32];
    zeroC(C0); zeroC(C1);
    gemm_r2(C0, C1, X, ta, lane);
    gemm_s2(C0, C1, buf, ta + W_TILE, lane);
    epi1(C0, bs, true, H, lane); epi1(C1, bs, true, H + 16, lane);
    zeroC(C0); zeroC(C1);
    gemm_r2(C0, C1, H, ta + 2 * W_TILE, lane);
    epi1(C0, bs + 64, false, H, lane); epi1(C1, bs + 64, false, H + 16, lane);
    st_buf2(buf, H, lane);
}
// x1 = smem (@W1a), x2 = regs (@W1b); result -> buf
static __device__ __forceinline__ void mlp2_sr(char* buf, const u32* X,
                                               const char* ta, const float* bs, int lane) {
    float C0[32], C1[32]; u32 H[32];
    zeroC(C0); zeroC(C1);
    gemm_s2(C0, C1, buf, ta, lane);
    gemm_r2(C0, C1, X, ta + W_TILE, lane);
    epi1(C0, bs, true, H, lane); epi1(C1, bs, true, H + 16, lane);
    zeroC(C0); zeroC(C1);
    gemm_r2(C0, C1, H, ta + 2 * W_TILE, lane);
    epi1(C0, bs + 64, false, H, lane); epi1(C1, bs + 64, false, H + 16, lane);
    st_buf2(buf, H, lane);
}
// both smem; result -> x1
static __device__ __forceinline__ void mlp2_ss(char* x1, char* x2, const char* ta,
                                               const float* bs, int lane) {
    float C0[32], C1[32]; u32 H[32];
    zeroC(C0); zeroC(C1);
    gemm_s2(C0, C1, x1, ta, lane);
    gemm_s2(C0, C1, x2, ta + W_TILE, lane);
    epi1(C0, bs, true, H, lane); epi1(C1, bs, true, H + 16, lane);
    zeroC(C0); zeroC(C1);
    gemm_r2(C0, C1, H, ta + 2 * W_TILE, lane);
    epi1(C0, bs + 64, false, H, lane); epi1(C1, bs + 64, false, H + 16, lane);
    st_buf2(x1, H, lane);
}
// x1 smem (PRESERVED) @W1a, x2 regs @W1b; cosine epilogue -> out (4 rows)
static __device__ __forceinline__ void mlp2_cos(char* x1, const u32* X,
                                                const char* ta, const float* bs,
                                                const float* tvs, float tvd,
                                                float* outp, int g0, int lane) {
    float C0[32], C1[32]; u32 H[32];
    zeroC(C0); zeroC(C1);
    gemm_s2(C0, C1, x1, ta, lane);
    gemm_r2(C0, C1, X, ta + W_TILE, lane);
    epi1(C0, bs, true, H, lane); epi1(C1, bs, true, H + 16, lane);
    zeroC(C0); zeroC(C1);
    gemm_r2(C0, C1, H, ta + 2 * W_TILE, lane);

    const float* b2 = bs + 64;
    const int cb = (lane & 3) * 2;
    float nu[4] = {0.f, 0.f, 0.f, 0.f}, nr[4] = {0.f, 0.f, 0.f, 0.f};
#pragma unroll
    for (int nt = 0; nt < 8; nt++) {
        const int c0 = 8 * nt + cb;
        const float bb0 = b2[c0], bb1 = b2[c0 + 1];
        const float t0 = tvs[c0], t1 = tvs[c0 + 1];
        const float* Cp[2] = { C0 + nt * 4, C1 + nt * 4 };
#pragma unroll
        for (int t = 0; t < 2; t++) {
            float v0 = fmaf(Cp[t][0], INVS, bb0), v1 = fmaf(Cp[t][1], INVS, bb1);
            float v2 = fmaf(Cp[t][2], INVS, bb0), v3 = fmaf(Cp[t][3], INVS, bb1);
            nu[2 * t + 0] = fmaf(v0, t0, fmaf(v1, t1, nu[2 * t + 0]));
            nr[2 * t + 0] = fmaf(v0, v0, fmaf(v1, v1, nr[2 * t + 0]));
            nu[2 * t + 1] = fmaf(v2, t0, fmaf(v3, t1, nu[2 * t + 1]));
            nr[2 * t + 1] = fmaf(v2, v2, fmaf(v3, v3, nr[2 * t + 1]));
        }
    }
#pragma unroll
    for (int off = 1; off <= 2; off <<= 1)
#pragma unroll
        for (int j = 0; j < 4; j++) {
            nu[j] += __shfl_xor_sync(~0u, nu[j], off);
            nr[j] += __shfl_xor_sync(~0u, nr[j], off);
        }
    if ((lane & 3) == 0) {
        const int rr[4] = { g0, g0 + 8, g0 + 16, g0 + 24 };
#pragma unroll
        for (int j = 0; j < 4; j++)
            if (rr[j] < BATCHN)
                outp[rr[j]] = nu[j] / (fmaxf(sqrtf(nr[j]), 1e-8f) * tvd) * 10.0f;
    }
}

__global__ void __launch_bounds__(TPB, 1)
logicnet_kernel(const int* __restrict__ seq,
                const int* __restrict__ pos_t,
                const int* __restrict__ neg_t,
                const float* __restrict__ item_embed,
                const float* __restrict__ g_tv,
                const float* __restrict__ nW1, const float* __restrict__ nb1,
                const float* __restrict__ nW2, const float* __restrict__ nb2,
                const float* __restrict__ aW1, const float* __restrict__ ab1,
                const float* __restrict__ aW2, const float* __restrict__ ab2,
                const float* __restrict__ oW1, const float* __restrict__ ob1,
                const float* __restrict__ oW2, const float* __restrict__ ob2,
                float* __restrict__ out) {
    const int tid = threadIdx.x, w = tid >> 5, lane = tid & 31;

    // ---- stage weights (x256, fp16) nt-paired: uint4 = {na.b0,na.b1,nb.b0,nb.b1} ----
    {
        const float* wsrc[8] = { nW1, nW2, aW1, aW1 + 4096, aW2, oW1, oW1 + 4096, oW2 };
#pragma unroll 1
        for (int e = tid; e < 4096; e += TPB) {
            const int t = e >> 9, rem = e & 511, ktnp = rem >> 5, ln = rem & 31;
            const int k0 = (ktnp >> 2) * 16 + (ln & 3) * 2;
            const int na = (ktnp & 3) * 16 + (ln >> 2);
            const int nb = na + 8;
            const float* s = wsrc[t];
            const u32 a0 = pkf16(s[(k0)     * 64 + na] * SSCALE, s[(k0 + 1) * 64 + na] * SSCALE);
            const u32 a1 = pkf16(s[(k0 + 8) * 64 + na] * SSCALE, s[(k0 + 9) * 64 + na] * SSCALE);
            const u32 b0 = pkf16(s[(k0)     * 64 + nb] * SSCALE, s[(k0 + 1) * 64 + nb] * SSCALE);
            const u32 b1 = pkf16(s[(k0 + 8) * 64 + nb] * SSCALE, s[(k0 + 9) * 64 + nb] * SSCALE);
            *(uint4*)(smc + OFF_W + (size_t)t * W_TILE + ((size_t)(ktnp * 32 + ln)) * 16) =
                make_uint4(a0, a1, b0, b1);
        }
        float* sb = (float*)(smc + OFF_BIAS);
        if (tid < 64) {
            sb[tid]       = nb1[tid] * SSCALE; sb[64 + tid]  = nb2[tid] * SSCALE;
            sb[128 + tid] = ab1[tid] * SSCALE; sb[192 + tid] = ab2[tid] * SSCALE;
            sb[256 + tid] = ob1[tid] * SSCALE; sb[320 + tid] = ob2[tid] * SSCALE;
            ((float*)(smc + OFF_TV))[tid] = g_tv[tid];
        }
    }
    __syncthreads();

    const float* BS  = (const float*)(smc + OFF_BIAS);
    const float* tvs = (const float*)(smc + OFF_TV);
    float t2 = 0.f;
#pragma unroll
    for (int c = 0; c < 64; c++) t2 = fmaf(tvs[c], tvs[c], t2);
    const float tvd = fmaxf(sqrtf(t2), 1e-8f);

    // warp owns 32 rows: g0=base+lane/4, +8 (tile0); +16, +24 (tile1)
    const int g0 = blockIdx.x * MROWS + w * 32 + (lane >> 2);
    const int q  = lane & 3;
    const int gA = min(g0,      BATCHN - 1);
    const int gB = min(g0 + 8,  BATCHN - 1);
    const int gC = min(g0 + 16, BATCHN - 1);
    const int gD = min(g0 + 24, BATCHN - 1);
    char* B0 = smc + OFF_A + w * 8192;
    char* B1 = B0 + 4096;

    u32 X[32];

#define EMB(id) (item_embed + (size_t)(id) * 64)
#define GSEQ(p) gather_r2(X, EMB(seq[gA * 5 + (p)]), EMB(seq[gB * 5 + (p)]), \
                             EMB(seq[gC * 5 + (p)]), EMB(seq[gD * 5 + (p)]), q)

    GSEQ(1);                                        // e(seq1)
    not_r(X, B0, BS + 0, lane);                     // n1 -> B0
    GSEQ(0);                                        // e(seq0)
    mlp2_rs(X, B0, WT(2), BS + 128, lane);          // int5 = AND(e0,n1) -> B0
    GSEQ(2);                                        // e(seq2)
    st_buf2(B1, X, lane);                           // e2 -> B1
    GSEQ(3);                                        // e(seq3)
    mlp2_sr(B1, X, WT(5), BS + 256, lane);          // int6 = OR(e2,e3) -> B1
    mlp2_ss(B0, B1, WT(2), BS + 128, lane);         // int7 = AND(int5,int6) -> B0
    not_s(B0, BS + 0, lane);                        // n7 -> B0
    GSEQ(4);                                        // e(seq4)
    mlp2_sr(B0, X, WT(5), BS + 256, lane);          // out = OR(n7,e4) -> B0
    not_s(B0, BS + 0, lane);                        // enc_not -> B0
    gather_r2(X, EMB(pos_t[gA]), EMB(pos_t[gB]), EMB(pos_t[gC]), EMB(pos_t[gD]), q);
    mlp2_cos(B0, X, WT(5), BS + 256, tvs, tvd, out, g0, lane);
    gather_r2(X, EMB(neg_t[gA]), EMB(neg_t[gB]), EMB(neg_t[gC]), EMB(neg_t[gD]), q);
    mlp2_cos(B0, X, WT(5), BS + 256, tvs, tvd, out + BATCHN, g0, lane);
}

extern "C" void kernel_launch(void* const* d_in, const int* in_sizes, int n_in,
                              void* d_out, int out_size) {
    (void)in_sizes; (void)n_in; (void)out_size;
    cudaFuncSetAttribute(logicnet_kernel,
                         cudaFuncAttributeMaxDynamicSharedMemorySize, SMEM_BYTES);
    logicnet_kernel<<<NBLOCKS, TPB, SMEM_BYTES>>>(
        (const int*)d_in[0], (const int*)d_in[1], (const int*)d_in[2],
        (const float*)d_in[3], (const float*)d_in[4],
        (const float*)d_in[5], (const float*)d_in[6],
        (const float*)d_in[7], (const float*)d_in[8],
        (const float*)d_in[9], (const float*)d_in[10],
        (const float*)d_in[11], (const float*)d_in[12],
        (const float*)d_in[13], (const float*)d_in[14],
        (const float*)d_in[15], (const float*)d_in[16],
        (float*)d_out);
}

// round 15
// speedup vs baseline: 3.3942x; 1.0276x over previous
#include <cuda_runtime.h>
#include <cuda_fp16.h>
#include <cstdint>

typedef uint32_t u32;

#define BATCHN 131072
#define WARPS  14
#define TPB    (WARPS * 32)
#define MROWS  (WARPS * 32)                      // 448 rows per CTA (32/warp)
#define NBLOCKS ((BATCHN + MROWS - 1) / MROWS)   // 293

#define SSCALE 256.0f
#define INVS   (1.0f / 256.0f)

// smem byte layout
#define OFF_W    0                // 8 weight tiles (fp16, nt-paired), 8KB each
#define W_TILE   8192
#define OFF_A    65536            // 14 warps x 1 buffer x 4KB (2 tiles x 2KB)
#define OFF_BIAS 122880           // 6 x 64 fp32 (pre-scaled x256)
#define OFF_TV   124416           // 64 fp32
#define SMEM_BYTES 124672

extern __shared__ char smc[];

static __device__ __forceinline__ void mma_f16(float* c, const u32* a, u32 b0, u32 b1) {
    asm volatile("mma.sync.aligned.m16n8k16.row.col.f32.f16.f16.f32 "
        "{%0,%1,%2,%3},{%4,%5,%6,%7},{%8,%9},{%0,%1,%2,%3};"
        : "+f"(c[0]), "+f"(c[1]), "+f"(c[2]), "+f"(c[3])
        : "r"(a[0]), "r"(a[1]), "r"(a[2]), "r"(a[3]), "r"(b0), "r"(b1));
}

static __device__ __forceinline__ u32 pkf16(float a, float b) {
    __half2 t = __floats2half2_rn(a, b);
    return *reinterpret_cast<u32*>(&t);
}
static __device__ __forceinline__ float lrelu(float v) {
    return v > 0.f ? v : 0.01f * v;
}
static __device__ __forceinline__ void zeroC(float* C) {
#pragma unroll
    for (int i = 0; i < 32; i++) C[i] = 0.f;
}

// activation buffer: tile t (0/1), ktile kt, lane -> uint4 slot; 4KB per buffer
#define ABIX(kt, t, lane) ((((kt) * 2 + (t)) * 32 + (lane)) << 4)

// ---- GEMM unit (64x64, fp16), 2 M-tiles, A from smem ----
static __device__ __forceinline__ void gemm_s2(float C0[32], float C1[32],
                                               const char* ab, const char* wt, int lane) {
#pragma unroll 2
    for (int kt = 0; kt < 4; kt++) {
        const uint4 A0 = *(const uint4*)(ab + ABIX(kt, 0, lane));
        const uint4 A1 = *(const uint4*)(ab + ABIX(kt, 1, lane));
#pragma unroll
        for (int np = 0; np < 4; np++) {
            const uint4 B = *(const uint4*)(wt + (((kt * 4 + np) * 32 + lane) << 4));
            mma_f16(C0 + (2 * np) * 4,     (const u32*)&A0, B.x, B.y);
            mma_f16(C0 + (2 * np + 1) * 4, (const u32*)&A0, B.z, B.w);
            mma_f16(C1 + (2 * np) * 4,     (const u32*)&A1, B.x, B.y);
            mma_f16(C1 + (2 * np + 1) * 4, (const u32*)&A1, B.z, B.w);
        }
    }
}
// ---- GEMM unit, A from registers (X = 32 regs: tile0 16, tile1 16) ----
static __device__ __forceinline__ void gemm_r2(float C0[32], float C1[32],
                                               const u32* X, const char* wt, int lane) {
#pragma unroll 2
    for (int kt = 0; kt < 4; kt++) {
#pragma unroll
        for (int np = 0; np < 4; np++) {
            const uint4 B = *(const uint4*)(wt + (((kt * 4 + np) * 32 + lane) << 4));
            mma_f16(C0 + (2 * np) * 4,     X + 4 * kt, B.x, B.y);
            mma_f16(C0 + (2 * np + 1) * 4, X + 4 * kt, B.z, B.w);
            mma_f16(C1 + (2 * np) * 4,     X + 16 + 4 * kt, B.x, B.y);
            mma_f16(C1 + (2 * np + 1) * 4, X + 16 + 4 * kt, B.z, B.w);
        }
    }
}

// ---- one tile's C (x 1/256, +scaled bias float2, opt lrelu) -> 16 A-frag regs ----
static __device__ __forceinline__ void epi1(const float C[32], const float* bias,
                                            bool relu, u32* H, int lane) {
    const int cb = (lane & 3) * 2;
#pragma unroll
    for (int nt = 0; nt < 8; nt++) {
        const float2 bb = *(const float2*)(bias + 8 * nt + cb);
        float v0 = fmaf(C[nt * 4 + 0], INVS, bb.x), v1 = fmaf(C[nt * 4 + 1], INVS, bb.y);
        float v2 = fmaf(C[nt * 4 + 2], INVS, bb.x), v3 = fmaf(C[nt * 4 + 3], INVS, bb.y);
        if (relu) { v0 = lrelu(v0); v1 = lrelu(v1); v2 = lrelu(v2); v3 = lrelu(v3); }
        const int o = (nt >> 1) * 4 + (nt & 1) * 2;
        H[o]     = pkf16(v0, v1);
        H[o + 1] = pkf16(v2, v3);
    }
}
// ---- 32 A-frag regs -> smem buffer (lane-private) ----
static __device__ __forceinline__ void st_buf2(char* dst, const u32* X, int lane) {
#pragma unroll
    for (int kt = 0; kt < 4; kt++) {
        *(uint4*)(dst + ABIX(kt, 0, lane)) =
            make_uint4(X[4 * kt], X[4 * kt + 1], X[4 * kt + 2], X[4 * kt + 3]);
        *(uint4*)(dst + ABIX(kt, 1, lane)) =
            make_uint4(X[16 + 4 * kt], X[17 + 4 * kt], X[18 + 4 * kt], X[19 + 4 * kt]);
    }
}
// ---- gather 4 embedding rows (x256, fp16) -> 32 A-frag regs ----
static __device__ __forceinline__ void gather_r2(u32* X, const float* e0, const float* e1,
                                                 const float* e2, const float* e3, int q) {
#pragma unroll
    for (int kt = 0; kt < 4; kt++) {
        float2 a = ((const float2*)e0)[8 * kt + q];
        float2 b = ((const float2*)e1)[8 * kt + q];
        float2 c = ((const float2*)e0)[8 * kt + q + 4];
        float2 d = ((const float2*)e1)[8 * kt + q + 4];
        X[4 * kt + 0] = pkf16(a.x * SSCALE, a.y * SSCALE);
        X[4 * kt + 1] = pkf16(b.x * SSCALE, b.y * SSCALE);
        X[4 * kt + 2] = pkf16(c.x * SSCALE, c.y * SSCALE);
        X[4 * kt + 3] = pkf16(d.x * SSCALE, d.y * SSCALE);
        float2 e = ((const float2*)e2)[8 * kt + q];
        float2 f = ((const float2*)e3)[8 * kt + q];
        float2 g = ((const float2*)e2)[8 * kt + q + 4];
        float2 h = ((const float2*)e3)[8 * kt + q + 4];
        X[16 + 4 * kt + 0] = pkf16(e.x * SSCALE, e.y * SSCALE);
        X[16 + 4 * kt + 1] = pkf16(f.x * SSCALE, f.y * SSCALE);
        X[16 + 4 * kt + 2] = pkf16(g.x * SSCALE, g.y * SSCALE);
        X[16 + 4 * kt + 3] = pkf16(h.x * SSCALE, h.y * SSCALE);
    }
}

#define WT(i) (smc + OFF_W + (i) * W_TILE)

// NOT, regs -> regs (out may alias in: all gemm reads happen before epi writes)
static __device__ __forceinline__ void not_rr(const u32* Xin, u32* Hout,
                                              const float* bs, int lane) {
    float C0[32], C1[32]; u32 T[32];
    zeroC(C0); zeroC(C1);
    gemm_r2(C0, C1, Xin, WT(0), lane);
    epi1(C0, bs, true, T, lane); epi1(C1, bs, true, T + 16, lane);
    zeroC(C0); zeroC(C1);
    gemm_r2(C0, C1, T, WT(1), lane);
    epi1(C0, bs + 64, false, Hout, lane); epi1(C1, bs + 64, false, Hout + 16, lane);
}
// AND/OR, both operands in regs (x1@W1a, x2@W1b) -> Hout regs (may alias x1/x2)
static __device__ __forceinline__ void mlp2_rr(const u32* X1, const u32* X2, u32* Hout,
                                               const char* ta, const float* bs, int lane) {
    float C0[32], C1[32]; u32 T[32];
    zeroC(C0); zeroC(C1);
    gemm_r2(C0, C1, X1, ta, lane);
    gemm_r2(C0, C1, X2, ta + W_TILE, lane);
    epi1(C0, bs, true, T, lane); epi1(C1, bs, true, T + 16, lane);
    zeroC(C0); zeroC(C1);
    gemm_r2(C0, C1, T, ta + 2 * W_TILE, lane);
    epi1(C0, bs + 64, false, Hout, lane); epi1(C1, bs + 64, false, Hout + 16, lane);
}
// AND/OR, x1 smem @W1a, x2 regs @W1b -> Hout regs
static __device__ __forceinline__ void mlp2_sr(const char* buf, const u32* X2, u32* Hout,
                                               const char* ta, const float* bs, int lane) {
    float C0[32], C1[32]; u32 T[32];
    zeroC(C0); zeroC(C1);
    gemm_s2(C0, C1, buf, ta, lane);
    gemm_r2(C0, C1, X2, ta + W_TILE, lane);
    epi1(C0, bs, true, T, lane); epi1(C1, bs, true, T + 16, lane);
    zeroC(C0); zeroC(C1);
    gemm_r2(C0, C1, T, ta + 2 * W_TILE, lane);
    epi1(C0, bs + 64, false, Hout, lane); epi1(C1, bs + 64, false, Hout + 16, lane);
}
// x1 smem (PRESERVED) @W1a, x2 regs @W1b; cosine epilogue -> out (4 rows)
static __device__ __forceinline__ void mlp2_cos(const char* x1, const u32* X,
                                                const char* ta, const float* bs,
                                                const float* tvs, float tvd,
                                                float* outp, int g0, int lane) {
    float C0[32], C1[32]; u32 T[32];
    zeroC(C0); zeroC(C1);
    gemm_s2(C0, C1, x1, ta, lane);
    gemm_r2(C0, C1, X, ta + W_TILE, lane);
    epi1(C0, bs, true, T, lane); epi1(C1, bs, true, T + 16, lane);
    zeroC(C0); zeroC(C1);
    gemm_r2(C0, C1, T, ta + 2 * W_TILE, lane);

    const float* b2 = bs + 64;
    const int cb = (lane & 3) * 2;
    float nu[4] = {0.f, 0.f, 0.f, 0.f}, nr[4] = {0.f, 0.f, 0.f, 0.f};
#pragma unroll
    for (int nt = 0; nt < 8; nt++) {
        const float2 bb = *(const float2*)(b2 + 8 * nt + cb);
        const float2 tv = *(const float2*)(tvs + 8 * nt + cb);
        const float* Cp[2] = { C0 + nt * 4, C1 + nt * 4 };
#pragma unroll
        for (int t = 0; t < 2; t++) {
            float v0 = fmaf(Cp[t][0], INVS, bb.x), v1 = fmaf(Cp[t][1], INVS, bb.y);
            float v2 = fmaf(Cp[t][2], INVS, bb.x), v3 = fmaf(Cp[t][3], INVS, bb.y);
            nu[2 * t + 0] = fmaf(v0, tv.x, fmaf(v1, tv.y, nu[2 * t + 0]));
            nr[2 * t + 0] = fmaf(v0, v0, fmaf(v1, v1, nr[2 * t + 0]));
            nu[2 * t + 1] = fmaf(v2, tv.x, fmaf(v3, tv.y, nu[2 * t + 1]));
            nr[2 * t + 1] = fmaf(v2, v2, fmaf(v3, v3, nr[2 * t + 1]));
        }
    }
#pragma unroll
    for (int off = 1; off <= 2; off <<= 1)
#pragma unroll
        for (int j = 0; j < 4; j++) {
            nu[j] += __shfl_xor_sync(~0u, nu[j], off);
            nr[j] += __shfl_xor_sync(~0u, nr[j], off);
        }
    if ((lane & 3) == 0) {
        const int rr[4] = { g0, g0 + 8, g0 + 16, g0 + 24 };
#pragma unroll
        for (int j = 0; j < 4; j++)
            if (rr[j] < BATCHN)
                outp[rr[j]] = nu[j] / (fmaxf(sqrtf(nr[j]), 1e-8f) * tvd) * 10.0f;
    }
}

__global__ void __launch_bounds__(TPB, 1)
logicnet_kernel(const int* __restrict__ seq,
                const int* __restrict__ pos_t,
                const int* __restrict__ neg_t,
                const float* __restrict__ item_embed,
                const float* __restrict__ g_tv,
                const float* __restrict__ nW1, const float* __restrict__ nb1,
                const float* __restrict__ nW2, const float* __restrict__ nb2,
                const float* __restrict__ aW1, const float* __restrict__ ab1,
                const float* __restrict__ aW2, const float* __restrict__ ab2,
                const float* __restrict__ oW1, const float* __restrict__ ob1,
                const float* __restrict__ oW2, const float* __restrict__ ob2,
                float* __restrict__ out) {
    const int tid = threadIdx.x, w = tid >> 5, lane = tid & 31;

    // ---- stage weights (x256, fp16) nt-paired: uint4 = {na.b0,na.b1,nb.b0,nb.b1} ----
    {
        const float* wsrc[8] = { nW1, nW2, aW1, aW1 + 4096, aW2, oW1, oW1 + 4096, oW2 };
#pragma unroll 1
        for (int e = tid; e < 4096; e += TPB) {
            const int t = e >> 9, rem = e & 511, ktnp = rem >> 5, ln = rem & 31;
            const int k0 = (ktnp >> 2) * 16 + (ln & 3) * 2;
            const int na = (ktnp & 3) * 16 + (ln >> 2);
            const int nb = na + 8;
            const float* s = wsrc[t];
            const u32 a0 = pkf16(s[(k0)     * 64 + na] * SSCALE, s[(k0 + 1) * 64 + na] * SSCALE);
            const u32 a1 = pkf16(s[(k0 + 8) * 64 + na] * SSCALE, s[(k0 + 9) * 64 + na] * SSCALE);
            const u32 b0 = pkf16(s[(k0)     * 64 + nb] * SSCALE, s[(k0 + 1) * 64 + nb] * SSCALE);
            const u32 b1 = pkf16(s[(k0 + 8) * 64 + nb] * SSCALE, s[(k0 + 9) * 64 + nb] * SSCALE);
            *(uint4*)(smc + OFF_W + (size_t)t * W_TILE + ((size_t)(ktnp * 32 + ln)) * 16) =
                make_uint4(a0, a1, b0, b1);
        }
        float* sb = (float*)(smc + OFF_BIAS);
        if (tid < 64) {
            sb[tid]       = nb1[tid] * SSCALE; sb[64 + tid]  = nb2[tid] * SSCALE;
            sb[128 + tid] = ab1[tid] * SSCALE; sb[192 + tid] = ab2[tid] * SSCALE;
            sb[256 + tid] = ob1[tid] * SSCALE; sb[320 + tid] = ob2[tid] * SSCALE;
            ((float*)(smc + OFF_TV))[tid] = g_tv[tid];
        }
    }
    __syncthreads();

    const float* BS  = (const float*)(smc + OFF_BIAS);
    const float* tvs = (const float*)(smc + OFF_TV);
    float t2 = 0.f;
#pragma unroll
    for (int c = 0; c < 64; c++) t2 = fmaf(tvs[c], tvs[c], t2);
    const float tvd = fmaxf(sqrtf(t2), 1e-8f);

    // warp owns 32 rows: g0=base+lane/4, +8 (tile0); +16, +24 (tile1)
    const int g0 = blockIdx.x * MROWS + w * 32 + (lane >> 2);
    const int q  = lane & 3;
    const int gA = min(g0,      BATCHN - 1);
    const int gB = min(g0 + 8,  BATCHN - 1);
    const int gC = min(g0 + 16, BATCHN - 1);
    const int gD = min(g0 + 24, BATCHN - 1);
    char* B0 = smc + OFF_A + w * 4096;

    u32 X[32], Y[32], H[32];

#define EMB(id) (item_embed + (size_t)(id) * 64)
#define GSEQ(dst, p) gather_r2(dst, EMB(seq[gA * 5 + (p)]), EMB(seq[gB * 5 + (p)]), \
                                    EMB(seq[gC * 5 + (p)]), EMB(seq[gD * 5 + (p)]), q)

    GSEQ(X, 1);                                   // e(seq1)
    not_rr(X, H, BS + 0, lane);                   // H = n1
    GSEQ(X, 0);                                   // e(seq0)
    mlp2_rr(X, H, H, WT(2), BS + 128, lane);      // H = int5 = AND(e0, n1)
    st_buf2(B0, H, lane);                         // int5 -> B0
    GSEQ(X, 2);                                   // e(seq2)
    GSEQ(Y, 3);                                   // e(seq3)
    mlp2_rr(X, Y, H, WT(5), BS + 256, lane);      // H = int6 = OR(e2, e3)
    mlp2_sr(B0, H, H, WT(2), BS + 128, lane);     // H = int7 = AND(int5, int6)
    not_rr(H, H, BS + 0, lane);                   // H = n7
    GSEQ(X, 4);                                   // e(seq4)
    mlp2_rr(H, X, H, WT(5), BS + 256, lane);      // H = out = OR(n7, e4)
    not_rr(H, H, BS + 0, lane);                   // H = enc_not
    st_buf2(B0, H, lane);                         // enc_not -> B0 (used twice)
    gather_r2(X, EMB(pos_t[gA]), EMB(pos_t[gB]), EMB(pos_t[gC]), EMB(pos_t[gD]), q);
    mlp2_cos(B0, X, WT(5), BS + 256, tvs, tvd, out, g0, lane);
    gather_r2(X, EMB(neg_t[gA]), EMB(neg_t[gB]), EMB(neg_t[gC]), EMB(neg_t[gD]), q);
    mlp2_cos(B0, X, WT(5), BS + 256, tvs, tvd, out + BATCHN, g0, lane);
}

extern "C" void kernel_launch(void* const* d_in, const int* in_sizes, int n_in,
                              void* d_out, int out_size) {
    (void)in_sizes; (void)n_in; (void)out_size;
    cudaFuncSetAttribute(logicnet_kernel,
                         cudaFuncAttributeMaxDynamicSharedMemorySize, SMEM_BYTES);
    logicnet_kernel<<<NBLOCKS, TPB, SMEM_BYTES>>>(
        (const int*)d_in[0], (const int*)d_in[1], (const int*)d_in[2],
        (const float*)d_in[3], (const float*)d_in[4],
        (const float*)d_in[5], (const float*)d_in[6],
        (const float*)d_in[7], (const float*)d_in[8],
        (const float*)d_in[9], (const float*)d_in[10],
        (const float*)d_in[11], (const float*)d_in[12],
        (const float*)d_in[13], (const float*)d_in[14],
        (const float*)d_in[15], (const float*)d_in[16],
        (float*)d_out);
}

// round 16
// speedup vs baseline: 3.5197x; 1.0370x over previous
#include <cuda_runtime.h>
#include <cuda_fp16.h>
#include <cstdint>

typedef uint32_t u32;

#define BATCHN 131072
#define WARPS  16
#define TPB    (WARPS * 32)
#define NCHUNK (BATCHN / 32)      // 4096 chunks of 32 rows
#define NBLOCKS 152

#define SSCALE 256.0f
#define INVS   (1.0f / 256.0f)

// smem byte layout
#define OFF_W    0                // 8 weight tiles (fp16, nt-paired), 8KB each
#define W_TILE   8192
#define OFF_A    65536            // 16 warps x 1 buffer x 4KB (2 tiles x 2KB)
#define OFF_BIAS 131072           // 6 x 64 fp32 (pre-scaled x256)
#define OFF_TV   132608           // 64 fp32
#define SMEM_BYTES 132864

extern __shared__ char smc[];

__device__ unsigned int g_ctr;

__global__ void reset_ctr() { g_ctr = 0; }

static __device__ __forceinline__ void mma_f16(float* c, const u32* a, u32 b0, u32 b1) {
    asm volatile("mma.sync.aligned.m16n8k16.row.col.f32.f16.f16.f32 "
        "{%0,%1,%2,%3},{%4,%5,%6,%7},{%8,%9},{%0,%1,%2,%3};"
        : "+f"(c[0]), "+f"(c[1]), "+f"(c[2]), "+f"(c[3])
        : "r"(a[0]), "r"(a[1]), "r"(a[2]), "r"(a[3]), "r"(b0), "r"(b1));
}

static __device__ __forceinline__ u32 pkf16(float a, float b) {
    __half2 t = __floats2half2_rn(a, b);
    return *reinterpret_cast<u32*>(&t);
}
static __device__ __forceinline__ u32 hrelu(u32 p) {
    // lrelu(v) = max(v, 0.01*v), elementwise on packed half2
    __half2 v = *reinterpret_cast<__half2*>(&p);
    const __half2 c = __floats2half2_rn(0.01f, 0.01f);
    __half2 r = __hmax2(v, __hmul2(v, c));
    return *reinterpret_cast<u32*>(&r);
}
static __device__ __forceinline__ void zeroC(float* C) {
#pragma unroll
    for (int i = 0; i < 32; i++) C[i] = 0.f;
}

// activation buffer: tile t (0/1), ktile kt, lane -> uint4 slot; 4KB per buffer
#define ABIX(kt, t, lane) ((((kt) * 2 + (t)) * 32 + (lane)) << 4)

// ---- GEMM unit (64x64, fp16), 2 M-tiles, A from smem ----
static __device__ __forceinline__ void gemm_s2(float C0[32], float C1[32],
                                               const char* ab, const char* wt, int lane) {
#pragma unroll 2
    for (int kt = 0; kt < 4; kt++) {
        const uint4 A0 = *(const uint4*)(ab + ABIX(kt, 0, lane));
        const uint4 A1 = *(const uint4*)(ab + ABIX(kt, 1, lane));
#pragma unroll
        for (int np = 0; np < 4; np++) {
            const uint4 B = *(const uint4*)(wt + (((kt * 4 + np) * 32 + lane) << 4));
            mma_f16(C0 + (2 * np) * 4,     (const u32*)&A0, B.x, B.y);
            mma_f16(C0 + (2 * np + 1) * 4, (const u32*)&A0, B.z, B.w);
            mma_f16(C1 + (2 * np) * 4,     (const u32*)&A1, B.x, B.y);
            mma_f16(C1 + (2 * np + 1) * 4, (const u32*)&A1, B.z, B.w);
        }
    }
}
// ---- GEMM unit, A from registers (X = 32 regs: tile0 16, tile1 16) ----
static __device__ __forceinline__ void gemm_r2(float C0[32], float C1[32],
                                               const u32* X, const char* wt, int lane) {
#pragma unroll 2
    for (int kt = 0; kt < 4; kt++) {
#pragma unroll
        for (int np = 0; np < 4; np++) {
            const uint4 B = *(const uint4*)(wt + (((kt * 4 + np) * 32 + lane) << 4));
            mma_f16(C0 + (2 * np) * 4,     X + 4 * kt, B.x, B.y);
            mma_f16(C0 + (2 * np + 1) * 4, X + 4 * kt, B.z, B.w);
            mma_f16(C1 + (2 * np) * 4,     X + 16 + 4 * kt, B.x, B.y);
            mma_f16(C1 + (2 * np + 1) * 4, X + 16 + 4 * kt, B.z, B.w);
        }
    }
}

// ---- C (x 1/256, +scaled bias) -> 16 A-frag regs; relu applied packed ----
static __device__ __forceinline__ void epi1(const float C[32], const float* bias,
                                            bool relu, u32* H, int lane) {
    const int cb = (lane & 3) * 2;
#pragma unroll
    for (int nt = 0; nt < 8; nt++) {
        const float2 bb = *(const float2*)(bias + 8 * nt + cb);
        const float v0 = fmaf(C[nt * 4 + 0], INVS, bb.x), v1 = fmaf(C[nt * 4 + 1], INVS, bb.y);
        const float v2 = fmaf(C[nt * 4 + 2], INVS, bb.x), v3 = fmaf(C[nt * 4 + 3], INVS, bb.y);
        const int o = (nt >> 1) * 4 + (nt & 1) * 2;
        u32 p0 = pkf16(v0, v1), p1 = pkf16(v2, v3);
        if (relu) { p0 = hrelu(p0); p1 = hrelu(p1); }
        H[o]     = p0;
        H[o + 1] = p1;
    }
}
// ---- 32 A-frag regs -> smem buffer (lane-private) ----
static __device__ __forceinline__ void st_buf2(char* dst, const u32* X, int lane) {
#pragma unroll
    for (int kt = 0; kt < 4; kt++) {
        *(uint4*)(dst + ABIX(kt, 0, lane)) =
            make_uint4(X[4 * kt], X[4 * kt + 1], X[4 * kt + 2], X[4 * kt + 3]);
        *(uint4*)(dst + ABIX(kt, 1, lane)) =
            make_uint4(X[16 + 4 * kt], X[17 + 4 * kt], X[18 + 4 * kt], X[19 + 4 * kt]);
    }
}
// ---- gather 4 embedding rows (x256, fp16) -> 32 A-frag regs ----
static __device__ __forceinline__ void gather_r2(u32* X, const float* e0, const float* e1,
                                                 const float* e2, const float* e3, int q) {
#pragma unroll
    for (int kt = 0; kt < 4; kt++) {
        float2 a = ((const float2*)e0)[8 * kt + q];
        float2 b = ((const float2*)e1)[8 * kt + q];
        float2 c = ((const float2*)e0)[8 * kt + q + 4];
        float2 d = ((const float2*)e1)[8 * kt + q + 4];
        X[4 * kt + 0] = pkf16(a.x * SSCALE, a.y * SSCALE);
        X[4 * kt + 1] = pkf16(b.x * SSCALE, b.y * SSCALE);
        X[4 * kt + 2] = pkf16(c.x * SSCALE, c.y * SSCALE);
        X[4 * kt + 3] = pkf16(d.x * SSCALE, d.y * SSCALE);
        float2 e = ((const float2*)e2)[8 * kt + q];
        float2 f = ((const float2*)e3)[8 * kt + q];
        float2 g = ((const float2*)e2)[8 * kt + q + 4];
        float2 h = ((const float2*)e3)[8 * kt + q + 4];
        X[16 + 4 * kt + 0] = pkf16(e.x * SSCALE, e.y * SSCALE);
        X[16 + 4 * kt + 1] = pkf16(f.x * SSCALE, f.y * SSCALE);
        X[16 + 4 * kt + 2] = pkf16(g.x * SSCALE, g.y * SSCALE);
        X[16 + 4 * kt + 3] = pkf16(h.x * SSCALE, h.y * SSCALE);
    }
}

#define WT(i) (smc + OFF_W + (i) * W_TILE)

// NOT, regs -> regs (out may alias in)
static __device__ __forceinline__ void not_rr(const u32* Xin, u32* Hout,
                                              const float* bs, int lane) {
    float C0[32], C1[32]; u32 T[32];
    zeroC(C0); zeroC(C1);
    gemm_r2(C0, C1, Xin, WT(0), lane);
    epi1(C0, bs, true, T, lane); epi1(C1, bs, true, T + 16, lane);
    zeroC(C0); zeroC(C1);
    gemm_r2(C0, C1, T, WT(1), lane);
    epi1(C0, bs + 64, false, Hout, lane); epi1(C1, bs + 64, false, Hout + 16, lane);
}
// AND/OR, both operands in regs -> Hout regs (may alias)
static __device__ __forceinline__ void mlp2_rr(const u32* X1, const u32* X2, u32* Hout,
                                               const char* ta, const float* bs, int lane) {
    float C0[32], C1[32]; u32 T[32];
    zeroC(C0); zeroC(C1);
    gemm_r2(C0, C1, X1, ta, lane);
    gemm_r2(C0, C1, X2, ta + W_TILE, lane);
    epi1(C0, bs, true, T, lane); epi1(C1, bs, true, T + 16, lane);
    zeroC(C0); zeroC(C1);
    gemm_r2(C0, C1, T, ta + 2 * W_TILE, lane);
    epi1(C0, bs + 64, false, Hout, lane); epi1(C1, bs + 64, false, Hout + 16, lane);
}
// AND/OR, x1 smem @W1a, x2 regs @W1b -> Hout regs
static __device__ __forceinline__ void mlp2_sr(const char* buf, const u32* X2, u32* Hout,
                                               const char* ta, const float* bs, int lane) {
    float C0[32], C1[32]; u32 T[32];
    zeroC(C0); zeroC(C1);
    gemm_s2(C0, C1, buf, ta, lane);
    gemm_r2(C0, C1, X2, ta + W_TILE, lane);
    epi1(C0, bs, true, T, lane); epi1(C1, bs, true, T + 16, lane);
    zeroC(C0); zeroC(C1);
    gemm_r2(C0, C1, T, ta + 2 * W_TILE, lane);
    epi1(C0, bs + 64, false, Hout, lane); epi1(C1, bs + 64, false, Hout + 16, lane);
}
// x1 smem (PRESERVED) @W1a, x2 regs @W1b; cosine epilogue -> out (4 rows)
static __device__ __forceinline__ void mlp2_cos(const char* x1, const u32* X,
                                                const char* ta, const float* bs,
                                                const float* tvs, float tvd,
                                                float* outp, int g0, int lane) {
    float C0[32], C1[32]; u32 T[32];
    zeroC(C0); zeroC(C1);
    gemm_s2(C0, C1, x1, ta, lane);
    gemm_r2(C0, C1, X, ta + W_TILE, lane);
    epi1(C0, bs, true, T, lane); epi1(C1, bs, true, T + 16, lane);
    zeroC(C0); zeroC(C1);
    gemm_r2(C0, C1, T, ta + 2 * W_TILE, lane);

    const float* b2 = bs + 64;
    const int cb = (lane & 3) * 2;
    float nu[4] = {0.f, 0.f, 0.f, 0.f}, nr[4] = {0.f, 0.f, 0.f, 0.f};
#pragma unroll
    for (int nt = 0; nt < 8; nt++) {
        const float2 bb = *(const float2*)(b2 + 8 * nt + cb);
        const float2 tv = *(const float2*)(tvs + 8 * nt + cb);
        const float* Cp[2] = { C0 + nt * 4, C1 + nt * 4 };
#pragma unroll
        for (int t = 0; t < 2; t++) {
            float v0 = fmaf(Cp[t][0], INVS, bb.x), v1 = fmaf(Cp[t][1], INVS, bb.y);
            float v2 = fmaf(Cp[t][2], INVS, bb.x), v3 = fmaf(Cp[t][3], INVS, bb.y);
            nu[2 * t + 0] = fmaf(v0, tv.x, fmaf(v1, tv.y, nu[2 * t + 0]));
            nr[2 * t + 0] = fmaf(v0, v0, fmaf(v1, v1, nr[2 * t + 0]));
            nu[2 * t + 1] = fmaf(v2, tv.x, fmaf(v3, tv.y, nu[2 * t + 1]));
            nr[2 * t + 1] = fmaf(v2, v2, fmaf(v3, v3, nr[2 * t + 1]));
        }
    }
#pragma unroll
    for (int off = 1; off <= 2; off <<= 1)
#pragma unroll
        for (int j = 0; j < 4; j++) {
            nu[j] += __shfl_xor_sync(~0u, nu[j], off);
            nr[j] += __shfl_xor_sync(~0u, nr[j], off);
        }
    if ((lane & 3) == 0) {
        outp[g0]      = nu[0] / (fmaxf(sqrtf(nr[0]), 1e-8f) * tvd) * 10.0f;
        outp[g0 + 8]  = nu[1] / (fmaxf(sqrtf(nr[1]), 1e-8f) * tvd) * 10.0f;
        outp[g0 + 16] = nu[2] / (fmaxf(sqrtf(nr[2]), 1e-8f) * tvd) * 10.0f;
        outp[g0 + 24] = nu[3] / (fmaxf(sqrtf(nr[3]), 1e-8f) * tvd) * 10.0f;
    }
}

__global__ void __launch_bounds__(TPB, 1)
logicnet_kernel(const int* __restrict__ seq,
                const int* __restrict__ pos_t,
                const int* __restrict__ neg_t,
                const float* __restrict__ item_embed,
                const float* __restrict__ g_tv,
                const float* __restrict__ nW1, const float* __restrict__ nb1,
                const float* __restrict__ nW2, const float* __restrict__ nb2,
                const float* __restrict__ aW1, const float* __restrict__ ab1,
                const float* __restrict__ aW2, const float* __restrict__ ab2,
                const float* __restrict__ oW1, const float* __restrict__ ob1,
                const float* __restrict__ oW2, const float* __restrict__ ob2,
                float* __restrict__ out) {
    const int tid = threadIdx.x, w = tid >> 5, lane = tid & 31;

    // ---- stage weights (x256, fp16) nt-paired: uint4 = {na.b0,na.b1,nb.b0,nb.b1} ----
    {
        const float* wsrc[8] = { nW1, nW2, aW1, aW1 + 4096, aW2, oW1, oW1 + 4096, oW2 };
#pragma unroll 1
        for (int e = tid; e < 4096; e += TPB) {
            const int t = e >> 9, rem = e & 511, ktnp = rem >> 5, ln = rem & 31;
            const int k0 = (ktnp >> 2) * 16 + (ln & 3) * 2;
            const int na = (ktnp & 3) * 16 + (ln >> 2);
            const int nb = na + 8;
            const float* s = wsrc[t];
            const u32 a0 = pkf16(s[(k0)     * 64 + na] * SSCALE, s[(k0 + 1) * 64 + na] * SSCALE);
            const u32 a1 = pkf16(s[(k0 + 8) * 64 + na] * SSCALE, s[(k0 + 9) * 64 + na] * SSCALE);
            const u32 b0 = pkf16(s[(k0)     * 64 + nb] * SSCALE, s[(k0 + 1) * 64 + nb] * SSCALE);
            const u32 b1 = pkf16(s[(k0 + 8) * 64 + nb] * SSCALE, s[(k0 + 9) * 64 + nb] * SSCALE);
            *(uint4*)(smc + OFF_W + (size_t)t * W_TILE + ((size_t)(ktnp * 32 + ln)) * 16) =
                make_uint4(a0, a1, b0, b1);
        }
        float* sb = (float*)(smc + OFF_BIAS);
        if (tid < 64) {
            sb[tid]       = nb1[tid] * SSCALE; sb[64 + tid]  = nb2[tid] * SSCALE;
            sb[128 + tid] = ab1[tid] * SSCALE; sb[192 + tid] = ab2[tid] * SSCALE;
            sb[256 + tid] = ob1[tid] * SSCALE; sb[320 + tid] = ob2[tid] * SSCALE;
            ((float*)(smc + OFF_TV))[tid] = g_tv[tid];
        }
    }
    __syncthreads();

    const float* BS  = (const float*)(smc + OFF_BIAS);
    const float* tvs = (const float*)(smc + OFF_TV);
    float t2 = 0.f;
#pragma unroll
    for (int c = 0; c < 64; c++) t2 = fmaf(tvs[c], tvs[c], t2);
    const float tvd = fmaxf(sqrtf(t2), 1e-8f);

    const int q = lane & 3;
    char* B0 = smc + OFF_A + w * 4096;

#define EMB(id) (item_embed + (size_t)(id) * 64)
#define GSEQ(dst, p) gather_r2(dst, EMB(seq[gA * 5 + (p)]), EMB(seq[gB * 5 + (p)]), \
                                    EMB(seq[gC * 5 + (p)]), EMB(seq[gD * 5 + (p)]), q)

    // ---- persistent work-stealing loop: each warp grabs 32-row chunks ----
#pragma unroll 1
    for (;;) {
        u32 c;
        if (lane == 0) c = atomicAdd(&g_ctr, 1u);
        c = __shfl_sync(~0u, c, 0);
        if (c >= NCHUNK) break;

        const int g0 = (int)c * 32 + (lane >> 2);
        const int gA = g0, gB = g0 + 8, gC = g0 + 16, gD = g0 + 24;

        u32 X[32], Y[32], H[32];

        GSEQ(X, 1);                                   // e(seq1)
        not_rr(X, H, BS + 0, lane);                   // H = n1
        GSEQ(X, 0);                                   // e(seq0)
        mlp2_rr(X, H, H, WT(2), BS + 128, lane);      // H = int5 = AND(e0, n1)
        st_buf2(B0, H, lane);                         // int5 -> B0
        GSEQ(X, 2);                                   // e(seq2)
        GSEQ(Y, 3);                                   // e(seq3)
        mlp2_rr(X, Y, H, WT(5), BS + 256, lane);      // H = int6 = OR(e2, e3)
        mlp2_sr(B0, H, H, WT(2), BS + 128, lane);     // H = int7 = AND(int5, int6)
        not_rr(H, H, BS + 0, lane);                   // H = n7
        GSEQ(X, 4);                                   // e(seq4)
        mlp2_rr(H, X, H, WT(5), BS + 256, lane);      // H = out = OR(n7, e4)
        not_rr(H, H, BS + 0, lane);                   // H = enc_not
        st_buf2(B0, H, lane);                         // enc_not -> B0 (used twice)
        gather_r2(X, EMB(pos_t[gA]), EMB(pos_t[gB]), EMB(pos_t[gC]), EMB(pos_t[gD]), q);
        mlp2_cos(B0, X, WT(5), BS + 256, tvs, tvd, out, g0, lane);
        gather_r2(X, EMB(neg_t[gA]), EMB(neg_t[gB]), EMB(neg_t[gC]), EMB(neg_t[gD]), q);
        mlp2_cos(B0, X, WT(5), BS + 256, tvs, tvd, out + BATCHN, g0, lane);
    }
}

extern "C" void kernel_launch(void* const* d_in, const int* in_sizes, int n_in,
                              void* d_out, int out_size) {
    (void)in_sizes; (void)n_in; (void)out_size;
    cudaFuncSetAttribute(logicnet_kernel,
                         cudaFuncAttributeMaxDynamicSharedMemorySize, SMEM_BYTES);
    reset_ctr<<<1, 1>>>();
    logicnet_kernel<<<NBLOCKS, TPB, SMEM_BYTES>>>(
        (const int*)d_in[0], (const int*)d_in[1], (const int*)d_in[2],
        (const float*)d_in[3], (const float*)d_in[4],
        (const float*)d_in[5], (const float*)d_in[6],
        (const float*)d_in[7], (const float*)d_in[8],
        (const float*)d_in[9], (const float*)d_in[10],
        (const float*)d_in[11], (const float*)d_in[12],
        (const float*)d_in[13], (const float*)d_in[14],
        (const float*)d_in[15], (const float*)d_in[16],
        (float*)d_out);
}